// round 14
// baseline (speedup 1.0000x reference)
#include <cuda_runtime.h>
#include <cstdint>

#define SEQ   4096
#define DM    1024
#define NH    16
#define HD    64
#define WIN   256

// Scratch (allocation-free: __device__ globals)
__device__ float g_q[SEQ * DM];
__device__ float g_k[SEQ * DM];
__device__ float g_v[SEQ * DM];
__device__ float g_att[SEQ * DM];
__device__ float g_xtf[SEQ * DM];        // x pre-rounded to tf32
__device__ float g_wtf[4 * DM * DM];     // Wq,Wk,Wv,Wo pre-rounded to tf32

// ---------------------------------------------------------------------------
// Common helpers
// ---------------------------------------------------------------------------
__device__ __forceinline__ uint32_t f2tf(float f) {
    uint32_t u;
    asm("cvt.rna.tf32.f32 %0, %1;" : "=r"(u) : "f"(f));
    return u;
}

__device__ __forceinline__ void mma_tf32(float (&d)[4],
                                         const uint32_t (&a)[4],
                                         const uint32_t (&b)[2]) {
    asm volatile(
        "mma.sync.aligned.m16n8k8.row.col.f32.tf32.tf32.f32 "
        "{%0,%1,%2,%3}, {%4,%5,%6,%7}, {%8,%9}, {%0,%1,%2,%3};\n"
        : "+f"(d[0]), "+f"(d[1]), "+f"(d[2]), "+f"(d[3])
        : "r"(a[0]), "r"(a[1]), "r"(a[2]), "r"(a[3]),
          "r"(b[0]), "r"(b[1]));
}

__device__ __forceinline__ void cp16(void* sdst, const float* gsrc) {
    uint32_t s = (uint32_t)__cvta_generic_to_shared(sdst);
    asm volatile("cp.async.cg.shared.global [%0], [%1], 16;\n"
                 :: "r"(s), "l"(gsrc));
}
__device__ __forceinline__ void cp_commit() {
    asm volatile("cp.async.commit_group;\n");
}
template <int N> __device__ __forceinline__ void cp_wait() {
    asm volatile("cp.async.wait_group %0;\n" :: "n"(N));
}

// ---------------------------------------------------------------------------
// tf32 pre-rounding kernels (cvt.rna once in GMEM, removed from mainloops).
// ---------------------------------------------------------------------------
__global__ __launch_bounds__(256)
void round_x_kernel(const float* __restrict__ src, float* __restrict__ dst)
{
    int i = blockIdx.x * 256 + threadIdx.x;   // n4 = SEQ*DM/4
    float4 v = ((const float4*)src)[i];
    uint4 w;
    w.x = f2tf(v.x); w.y = f2tf(v.y); w.z = f2tf(v.z); w.w = f2tf(v.w);
    ((uint4*)dst)[i] = w;
}

__global__ __launch_bounds__(256)
void round_w_kernel(const float* __restrict__ W0, const float* __restrict__ W1,
                    const float* __restrict__ W2, const float* __restrict__ W3,
                    float* __restrict__ dst)
{
    const float* W = (blockIdx.z == 0) ? W0 : (blockIdx.z == 1) ? W1
                   : (blockIdx.z == 2) ? W2 : W3;
    int i = blockIdx.x * 256 + threadIdx.x;   // n4 = DM*DM/4
    float4 v = ((const float4*)W)[i];
    uint4 w;
    w.x = f2tf(v.x); w.y = f2tf(v.y); w.z = f2tf(v.z); w.w = f2tf(v.w);
    ((uint4*)(dst + (size_t)blockIdx.z * DM * DM))[i] = w;
}

// ---------------------------------------------------------------------------
// tf32 tensor-core GEMM with bias. GBK=64 (8 k-slices per barrier epoch),
// 2-stage cp.async pipeline, 1 CTA/SM (regs unconstrained -> no spills).
// K-slice order globally unchanged vs the verified GBK=32 kernel ->
// bit-identical accumulation.
// SMEM (raw f32 -> tf32 at fragment load is NOT needed: inputs pre-rounded):
//   A stage [128][68] row-major  (frag banks 4*gid+tig: conflict-free)
//   B stage [64][136]            (frag banks 8*tig+gid: conflict-free)
// ---------------------------------------------------------------------------
#define GBM 128
#define GBN 128
#define GBK 64
#define SAW 68
#define SBW 136
#define ASZ (GBM * SAW)            // 8704 floats
#define BSZ (GBK * SBW)            // 8704 floats
#define GSTAGES 2
#define GEMM_SMEM_BYTES (GSTAGES * (ASZ + BSZ) * 4)   // 139264

template <bool ROUND_C>
__global__ __launch_bounds__(256, 1)
void gemm_tf32_bias(const float* __restrict__ A,
                    const float* __restrict__ B0, const float* __restrict__ B1,
                    const float* __restrict__ B2,
                    const float* __restrict__ b0, const float* __restrict__ b1,
                    const float* __restrict__ b2,
                    float* __restrict__ C0, float* __restrict__ C1,
                    float* __restrict__ C2,
                    int M, int N, int K)
{
    const float* B    = (blockIdx.z == 0) ? B0 : ((blockIdx.z == 1) ? B1 : B2);
    const float* bias = (blockIdx.z == 0) ? b0 : ((blockIdx.z == 1) ? b1 : b2);
    float*       C    = (blockIdx.z == 0) ? C0 : ((blockIdx.z == 1) ? C1 : C2);

    extern __shared__ float smg[];
    float* SAbase = smg;
    float* SBbase = smg + GSTAGES * ASZ;

    const int tid  = threadIdx.x;
    const int wid  = tid >> 5;
    const int lane = tid & 31;
    const int wm   = wid & 1;
    const int wn   = wid >> 1;
    const int gid  = lane >> 2;
    const int tig  = lane & 3;

    const float* Aptr = A + (long)blockIdx.y * GBM * K;
    const float* Bptr = B + blockIdx.x * GBN;

    // Staging decomposition: A 128x64 floats (2048 chunks), 2 thr/row x 8
    // chunks; B 64x128 floats (2048 chunks), 4 thr/row x 8 chunks.
    const int arow = tid >> 1;            // 0..127
    const int ac   = (tid & 1) * 4;       // 0 or 4; +8j covers 64 cols
    const int brow = tid >> 2;            // 0..63
    const int bc   = (tid & 3) * 4;       // 0..12; +16j covers 128 cols

    float acc[4][4][4];
#pragma unroll
    for (int mi = 0; mi < 4; mi++)
#pragma unroll
        for (int ni = 0; ni < 4; ni++)
#pragma unroll
            for (int r = 0; r < 4; r++) acc[mi][ni][r] = 0.f;

    const int NT = K / GBK;   // 16

#define GEMM_ISSUE(KT, S)                                                     \
    do {                                                                      \
        float* as_ = SAbase + (S) * ASZ;                                      \
        float* bs_ = SBbase + (S) * BSZ;                                      \
        _Pragma("unroll")                                                     \
        for (int j_ = 0; j_ < 8; j_++) {                                      \
            int c_ = ac + 8 * j_;                                             \
            cp16(as_ + arow * SAW + c_,                                       \
                 Aptr + (long)arow * K + (KT) * GBK + c_);                    \
        }                                                                     \
        _Pragma("unroll")                                                     \
        for (int j_ = 0; j_ < 8; j_++) {                                      \
            int c_ = bc + 16 * j_;                                            \
            cp16(bs_ + brow * SBW + c_,                                       \
                 Bptr + (long)((KT) * GBK + brow) * N + c_);                  \
        }                                                                     \
    } while (0)

#define LOAD_FRAGS(BUF, KB)                                                   \
    do {                                                                      \
        _Pragma("unroll")                                                     \
        for (int mi = 0; mi < 4; mi++) {                                      \
            int m = wm * 64 + mi * 16 + gid;                                  \
            af[BUF][mi][0] = asu[(m)     * SAW + (KB) + tig];                 \
            af[BUF][mi][1] = asu[(m + 8) * SAW + (KB) + tig];                 \
            af[BUF][mi][2] = asu[(m)     * SAW + (KB) + tig + 4];             \
            af[BUF][mi][3] = asu[(m + 8) * SAW + (KB) + tig + 4];             \
        }                                                                     \
        _Pragma("unroll")                                                     \
        for (int ni = 0; ni < 4; ni++) {                                      \
            int n = wn * 32 + ni * 8 + gid;                                   \
            bf[BUF][ni][0] = bsu[((KB) + tig)     * SBW + n];                 \
            bf[BUF][ni][1] = bsu[((KB) + tig + 4) * SBW + n];                 \
        }                                                                     \
    } while (0)

    GEMM_ISSUE(0, 0); cp_commit();

    for (int kt = 0; kt < NT; kt++) {
        const int s = kt & 1;
        cp_wait<0>();          // stage s (group issued last iteration) landed
        __syncthreads();       // all warps done reading stage s^1 (tile kt-1)
        if (kt + 1 < NT) { GEMM_ISSUE(kt + 1, s ^ 1); cp_commit(); }

        const uint32_t* asu = (const uint32_t*)(SAbase + s * ASZ);
        const uint32_t* bsu = (const uint32_t*)(SBbase + s * BSZ);

        uint32_t af[2][4][4], bf[2][4][2];
        LOAD_FRAGS(0, 0);
#pragma unroll
        for (int ks = 0; ks < 8; ks++) {
            const int cur = ks & 1;
            if (ks < 7) {
                const int nxt = cur ^ 1;
                LOAD_FRAGS(nxt, (ks + 1) * 8);
            }
#pragma unroll
            for (int mi = 0; mi < 4; mi++)
#pragma unroll
                for (int ni = 0; ni < 4; ni++)
                    mma_tf32(acc[mi][ni], af[cur][mi], bf[cur][ni]);
        }
    }
#undef GEMM_ISSUE
#undef LOAD_FRAGS

    const int row_base = blockIdx.y * GBM + wm * 64;
    const int col_base = blockIdx.x * GBN + wn * 32;
#pragma unroll
    for (int mi = 0; mi < 4; mi++) {
#pragma unroll
        for (int ni = 0; ni < 4; ni++) {
            int r0 = row_base + mi * 16 + gid;
            int c  = col_base + ni * 8 + 2 * tig;
            float2 bv = *(const float2*)&bias[c];
            float2 o01, o23;
            o01.x = acc[mi][ni][0] + bv.x;
            o01.y = acc[mi][ni][1] + bv.y;
            o23.x = acc[mi][ni][2] + bv.x;
            o23.y = acc[mi][ni][3] + bv.y;
            if (ROUND_C) {
                o01.x = __uint_as_float(f2tf(o01.x));
                o01.y = __uint_as_float(f2tf(o01.y));
                o23.x = __uint_as_float(f2tf(o23.x));
                o23.y = __uint_as_float(f2tf(o23.y));
            }
            *(float2*)&C[(long)r0 * N + c]       = o01;
            *(float2*)&C[(long)(r0 + 8) * N + c] = o23;
        }
    }
}

// ---------------------------------------------------------------------------
// Tensor-core sliding-window flash attention (unchanged from R13 pass).
// QT=64 queries per CTA, 128 threads (4 warps x 16 query rows), 2 CTAs/SM.
// K natural [key][d] stride 68, V natural stride 72; cp.async double-buffered.
// ---------------------------------------------------------------------------
#define QT    64
#define ATHR  128
#define SQ_   68
#define SK_   68
#define SV_   72
#define KSZ   (64 * SK_)
#define VSZ   (64 * SV_)
#define ATT_SMEM_BYTES ((2 * QT * SQ_ + 2 * KSZ + 2 * VSZ) * 4)   // 106496

__global__ __launch_bounds__(ATHR, 2)
void attn_tc()
{
    extern __shared__ float sma[];
    uint32_t* Qs = (uint32_t*)sma;                 // [64][68] tf32 (scaled)
    uint32_t* Ps = Qs + QT * SQ_;                  // [64][68] tf32
    float*    Ks = sma + 2 * QT * SQ_;             // 2 x [64 key][68]
    float*    Vs = Ks + 2 * KSZ;                   // 2 x [64 key][72]

    const int h    = blockIdx.y;
    const int qt   = blockIdx.x;
    const int q0   = qt * QT;
    const int tid  = threadIdx.x;
    const int wid  = tid >> 5;                     // 0..3
    const int lane = tid & 31;
    const int gid  = lane >> 2;
    const int tig  = lane & 3;
    const int col  = h * HD;
    const int qw   = wid * 16;

    const int srow = tid >> 1;            // 0..63  (staging row = key)
    const int sc4  = (tid & 1) * 4;       // base col chunk; +8j covers row

    int kt_lo = qt - 4; if (kt_lo < 0) kt_lo = 0;
    const int kt_hi = qt;

#define ATT_STAGE(KT, S)                                                      \
    do {                                                                      \
        long gb_ = (long)((KT) * 64 + srow) * DM + col;                       \
        float* kd_ = Ks + (S) * KSZ + srow * SK_;                             \
        float* vd_ = Vs + (S) * VSZ + srow * SV_;                             \
        _Pragma("unroll")                                                     \
        for (int j_ = 0; j_ < 8; j_++) {                                      \
            int c_ = sc4 + 8 * j_;                                            \
            cp16(kd_ + c_, &g_k[gb_ + c_]);                                   \
            cp16(vd_ + c_, &g_v[gb_ + c_]);                                   \
        }                                                                     \
    } while (0)

    // Prefetch first two tiles (window always spans >= 2 tiles).
    ATT_STAGE(kt_lo, 0);     cp_commit();
    ATT_STAGE(kt_lo + 1, 1); cp_commit();

    // Load + scale Q tile (overlaps with the in-flight K/V copies).
    for (int i = tid; i < QT * 16; i += ATHR) {
        int row = i >> 4;
        int c4  = (i & 15) * 4;
        float4 v = *(const float4*)&g_q[(long)(q0 + row) * DM + col + c4];
        uint32_t* dst = &Qs[row * SQ_ + c4];
        dst[0] = __float_as_uint(v.x * 0.125f);   // exact: q already tf32
        dst[1] = __float_as_uint(v.y * 0.125f);
        dst[2] = __float_as_uint(v.z * 0.125f);
        dst[3] = __float_as_uint(v.w * 0.125f);
    }

    const int prow0 = (qw + gid) * SQ_;
    const int prow1 = (qw + gid + 8) * SQ_;

    float m0 = -1e30f, m1 = -1e30f, l0 = 0.f, l1 = 0.f;
    float o[8][4];
#pragma unroll
    for (int ni = 0; ni < 8; ni++)
#pragma unroll
        for (int r = 0; r < 4; r++) o[ni][r] = 0.f;

    for (int kt = kt_lo; kt <= kt_hi; kt++) {
        const int s = (kt - kt_lo) & 1;
        if (kt + 1 <= kt_hi) cp_wait<1>(); else cp_wait<0>();
        __syncthreads();   // stage s data visible to all warps (covers Qs too)

        const uint32_t* ks = (const uint32_t*)(Ks + s * KSZ);
        const uint32_t* vs = (const uint32_t*)(Vs + s * VSZ);

        // S = Q @ K^T  (K natural layout: element (k,n) at ks[n*SK_ + k])
        float sr[8][4];
#pragma unroll
        for (int ni = 0; ni < 8; ni++)
#pragma unroll
            for (int r = 0; r < 4; r++) sr[ni][r] = 0.f;

#pragma unroll
        for (int ksl = 0; ksl < 8; ksl++) {
            const int kb = ksl * 8;
            uint32_t a[4];
            a[0] = Qs[prow0 + kb + tig];
            a[1] = Qs[prow1 + kb + tig];
            a[2] = Qs[prow0 + kb + tig + 4];
            a[3] = Qs[prow1 + kb + tig + 4];
            uint32_t b[8][2];
#pragma unroll
            for (int ni = 0; ni < 8; ni++) {
                int n = ni * 8 + gid;
                b[ni][0] = ks[n * SK_ + kb + tig];
                b[ni][1] = ks[n * SK_ + kb + tig + 4];
            }
#pragma unroll
            for (int ni = 0; ni < 8; ni++) mma_tf32(sr[ni], a, b[ni]);
        }

        // Mask + row stats.
        const int iq0 = q0 + qw + gid;
        const int iq1 = iq0 + 8;
        float tmax0 = -1e30f, tmax1 = -1e30f;
#pragma unroll
        for (int ni = 0; ni < 8; ni++) {
            int jg = kt * 64 + ni * 8 + 2 * tig;
            bool k0, k1;
            k0 = (jg     <= iq0) && (iq0 - jg     < WIN);
            k1 = (jg + 1 <= iq0) && (iq0 - jg - 1 < WIN);
            sr[ni][0] = k0 ? sr[ni][0] : -1e30f;
            sr[ni][1] = k1 ? sr[ni][1] : -1e30f;
            k0 = (jg     <= iq1) && (iq1 - jg     < WIN);
            k1 = (jg + 1 <= iq1) && (iq1 - jg - 1 < WIN);
            sr[ni][2] = k0 ? sr[ni][2] : -1e30f;
            sr[ni][3] = k1 ? sr[ni][3] : -1e30f;
            tmax0 = fmaxf(tmax0, fmaxf(sr[ni][0], sr[ni][1]));
            tmax1 = fmaxf(tmax1, fmaxf(sr[ni][2], sr[ni][3]));
        }
        tmax0 = fmaxf(tmax0, __shfl_xor_sync(0xffffffffu, tmax0, 1));
        tmax0 = fmaxf(tmax0, __shfl_xor_sync(0xffffffffu, tmax0, 2));
        tmax1 = fmaxf(tmax1, __shfl_xor_sync(0xffffffffu, tmax1, 1));
        tmax1 = fmaxf(tmax1, __shfl_xor_sync(0xffffffffu, tmax1, 2));

        float mn0 = fmaxf(m0, tmax0), mn1 = fmaxf(m1, tmax1);
        float corr0 = __expf(m0 - mn0), corr1 = __expf(m1 - mn1);
        m0 = mn0; m1 = mn1;

        float ls0 = 0.f, ls1 = 0.f;
#pragma unroll
        for (int ni = 0; ni < 8; ni++) {
            int c = ni * 8 + 2 * tig;
            float p0 = (sr[ni][0] > -1e29f) ? __expf(sr[ni][0] - m0) : 0.f;
            float p1 = (sr[ni][1] > -1e29f) ? __expf(sr[ni][1] - m0) : 0.f;
            float p2 = (sr[ni][2] > -1e29f) ? __expf(sr[ni][2] - m1) : 0.f;
            float p3 = (sr[ni][3] > -1e29f) ? __expf(sr[ni][3] - m1) : 0.f;
            Ps[prow0 + c]     = f2tf(p0);
            Ps[prow0 + c + 1] = f2tf(p1);
            Ps[prow1 + c]     = f2tf(p2);
            Ps[prow1 + c + 1] = f2tf(p3);
            ls0 += p0 + p1;
            ls1 += p2 + p3;
        }
        ls0 += __shfl_xor_sync(0xffffffffu, ls0, 1);
        ls0 += __shfl_xor_sync(0xffffffffu, ls0, 2);
        ls1 += __shfl_xor_sync(0xffffffffu, ls1, 1);
        ls1 += __shfl_xor_sync(0xffffffffu, ls1, 2);
        l0 = l0 * corr0 + ls0;
        l1 = l1 * corr1 + ls1;
#pragma unroll
        for (int ni = 0; ni < 8; ni++) {
            o[ni][0] *= corr0; o[ni][1] *= corr0;
            o[ni][2] *= corr1; o[ni][3] *= corr1;
        }

        __syncwarp();   // Ps rows are per-warp private

        // O += P @ V  (V natural: element (k,n) at vs[k*SV_ + n])
#pragma unroll
        for (int ksl = 0; ksl < 8; ksl++) {
            const int kb = ksl * 8;
            uint32_t a[4];
            a[0] = Ps[prow0 + kb + tig];
            a[1] = Ps[prow1 + kb + tig];
            a[2] = Ps[prow0 + kb + tig + 4];
            a[3] = Ps[prow1 + kb + tig + 4];
            uint32_t b[8][2];
#pragma unroll
            for (int ni = 0; ni < 8; ni++) {
                int n = ni * 8 + gid;
                b[ni][0] = vs[(kb + tig) * SV_ + n];
                b[ni][1] = vs[(kb + tig + 4) * SV_ + n];
            }
#pragma unroll
            for (int ni = 0; ni < 8; ni++) mma_tf32(o[ni], a, b[ni]);
        }

        __syncthreads();   // all warps done reading stage s
        if (kt + 2 <= kt_hi) { ATT_STAGE(kt + 2, s); cp_commit(); }
    }
#undef ATT_STAGE

    // Epilogue: normalize, round to tf32 (consumer is the tf32 Wo GEMM).
    const float inv0 = 1.f / l0, inv1 = 1.f / l1;
    const int r0 = q0 + qw + gid;
#pragma unroll
    for (int ni = 0; ni < 8; ni++) {
        int c = col + ni * 8 + 2 * tig;
        float2 w0, w1;
        w0.x = __uint_as_float(f2tf(o[ni][0] * inv0));
        w0.y = __uint_as_float(f2tf(o[ni][1] * inv0));
        w1.x = __uint_as_float(f2tf(o[ni][2] * inv1));
        w1.y = __uint_as_float(f2tf(o[ni][3] * inv1));
        *(float2*)&g_att[(long)r0 * DM + c]       = w0;
        *(float2*)&g_att[(long)(r0 + 8) * DM + c] = w1;
    }
}

// ---------------------------------------------------------------------------
// Launch. Input order resolved at runtime from in_sizes (weights DM*DM,
// biases DM): grouped setup_inputs order or interleaved pair order.
// ---------------------------------------------------------------------------
extern "C" void kernel_launch(void* const* d_in, const int* in_sizes, int n_in,
                              void* d_out, int out_size)
{
    const float* x = (const float*)d_in[0];
    const float *Wq, *Wk, *Wv, *Wo, *bq, *bk, *bv, *bo;

    if (in_sizes[2] == DM) {
        Wq = (const float*)d_in[1]; bq = (const float*)d_in[2];
        Wk = (const float*)d_in[3]; bk = (const float*)d_in[4];
        Wv = (const float*)d_in[5]; bv = (const float*)d_in[6];
        Wo = (const float*)d_in[7]; bo = (const float*)d_in[8];
    } else {
        Wq = (const float*)d_in[1]; Wk = (const float*)d_in[2];
        Wv = (const float*)d_in[3]; Wo = (const float*)d_in[4];
        bq = (const float*)d_in[5]; bk = (const float*)d_in[6];
        bv = (const float*)d_in[7]; bo = (const float*)d_in[8];
    }
    float* out = (float*)d_out;

    float *q, *k, *v, *att, *xtf, *wtf;
    cudaGetSymbolAddress((void**)&q,   g_q);
    cudaGetSymbolAddress((void**)&k,   g_k);
    cudaGetSymbolAddress((void**)&v,   g_v);
    cudaGetSymbolAddress((void**)&att, g_att);
    cudaGetSymbolAddress((void**)&xtf, g_xtf);
    cudaGetSymbolAddress((void**)&wtf, g_wtf);

    cudaFuncSetAttribute(gemm_tf32_bias<true>,
                         cudaFuncAttributeMaxDynamicSharedMemorySize,
                         GEMM_SMEM_BYTES);
    cudaFuncSetAttribute(gemm_tf32_bias<false>,
                         cudaFuncAttributeMaxDynamicSharedMemorySize,
                         GEMM_SMEM_BYTES);
    cudaFuncSetAttribute(attn_tc,
                         cudaFuncAttributeMaxDynamicSharedMemorySize,
                         ATT_SMEM_BYTES);

    // Pre-round x and weights to tf32 (bit-identical to mainloop cvt.rna).
    round_x_kernel<<<SEQ * DM / 4 / 256, 256>>>(x, xtf);
    dim3 gw(DM * DM / 4 / 256, 1, 4);
    round_w_kernel<<<gw, 256>>>(Wq, Wk, Wv, Wo, wtf);

    const float* wq = wtf;
    const float* wk = wtf + (size_t)DM * DM;
    const float* wv = wtf + (size_t)2 * DM * DM;
    const float* wo = wtf + (size_t)3 * DM * DM;

    dim3 gqkv(DM / GBN, SEQ / GBM, 3);
    gemm_tf32_bias<true><<<gqkv, 256, GEMM_SMEM_BYTES>>>(
        xtf, wq, wk, wv, bq, bk, bv, q, k, v, SEQ, DM, DM);

    dim3 gat(SEQ / QT, NH);
    attn_tc<<<gat, ATHR, ATT_SMEM_BYTES>>>();

    dim3 gout(DM / GBN, SEQ / GBM, 1);
    gemm_tf32_bias<false><<<gout, 256, GEMM_SMEM_BYTES>>>(
        att, wo, wo, wo, bo, bo, bo, out, out, out, SEQ, DM, DM);
}

// round 15
// speedup vs baseline: 1.2504x; 1.2504x over previous
#include <cuda_runtime.h>
#include <cstdint>

#define SEQ   4096
#define DM    1024
#define NH    16
#define HD    64
#define WIN   256

// Scratch (allocation-free: __device__ globals)
__device__ float g_q[SEQ * DM];
__device__ float g_k[SEQ * DM];
__device__ float g_v[SEQ * DM];
__device__ float g_att[SEQ * DM];
__device__ float g_xtf[SEQ * DM];        // x pre-rounded to tf32
__device__ float g_wtf[4 * DM * DM];     // Wq,Wk,Wv,Wo pre-rounded to tf32

// ---------------------------------------------------------------------------
// Common helpers
// ---------------------------------------------------------------------------
__device__ __forceinline__ uint32_t f2tf(float f) {
    uint32_t u;
    asm("cvt.rna.tf32.f32 %0, %1;" : "=r"(u) : "f"(f));
    return u;
}

__device__ __forceinline__ void mma_tf32(float (&d)[4],
                                         const uint32_t (&a)[4],
                                         const uint32_t (&b)[2]) {
    asm volatile(
        "mma.sync.aligned.m16n8k8.row.col.f32.tf32.tf32.f32 "
        "{%0,%1,%2,%3}, {%4,%5,%6,%7}, {%8,%9}, {%0,%1,%2,%3};\n"
        : "+f"(d[0]), "+f"(d[1]), "+f"(d[2]), "+f"(d[3])
        : "r"(a[0]), "r"(a[1]), "r"(a[2]), "r"(a[3]),
          "r"(b[0]), "r"(b[1]));
}

__device__ __forceinline__ void cp16(void* sdst, const float* gsrc) {
    uint32_t s = (uint32_t)__cvta_generic_to_shared(sdst);
    asm volatile("cp.async.cg.shared.global [%0], [%1], 16;\n"
                 :: "r"(s), "l"(gsrc));
}
__device__ __forceinline__ void cp_commit() {
    asm volatile("cp.async.commit_group;\n");
}
template <int N> __device__ __forceinline__ void cp_wait() {
    asm volatile("cp.async.wait_group %0;\n" :: "n"(N));
}

// ---------------------------------------------------------------------------
// tf32 pre-rounding kernels (cvt.rna once in GMEM, removed from mainloops).
// ---------------------------------------------------------------------------
__global__ __launch_bounds__(256)
void round_x_kernel(const float* __restrict__ src, float* __restrict__ dst)
{
    int i = blockIdx.x * 256 + threadIdx.x;   // n4 = SEQ*DM/4
    float4 v = ((const float4*)src)[i];
    uint4 w;
    w.x = f2tf(v.x); w.y = f2tf(v.y); w.z = f2tf(v.z); w.w = f2tf(v.w);
    ((uint4*)dst)[i] = w;
}

__global__ __launch_bounds__(256)
void round_w_kernel(const float* __restrict__ W0, const float* __restrict__ W1,
                    const float* __restrict__ W2, const float* __restrict__ W3,
                    float* __restrict__ dst)
{
    const float* W = (blockIdx.z == 0) ? W0 : (blockIdx.z == 1) ? W1
                   : (blockIdx.z == 2) ? W2 : W3;
    int i = blockIdx.x * 256 + threadIdx.x;   // n4 = DM*DM/4
    float4 v = ((const float4*)W)[i];
    uint4 w;
    w.x = f2tf(v.x); w.y = f2tf(v.y); w.z = f2tf(v.z); w.w = f2tf(v.w);
    ((uint4*)(dst + (size_t)blockIdx.z * DM * DM))[i] = w;
}

// ---------------------------------------------------------------------------
// tf32 tensor-core GEMM with bias, 3-stage cp.async pipeline.
// EXACT revert to the R13-verified configuration (GBK=32, 2 CTAs/SM).
// ---------------------------------------------------------------------------
#define GBM 128
#define GBN 128
#define GBK 32
#define SAW 36
#define SBW 136
#define ASZ (GBM * SAW)
#define BSZ (GBK * SBW)
#define GSTAGES 3
#define GEMM_SMEM_BYTES (GSTAGES * (ASZ + BSZ) * 4)   // 107520

template <bool ROUND_C>
__global__ __launch_bounds__(256, 2)
void gemm_tf32_bias(const float* __restrict__ A,
                    const float* __restrict__ B0, const float* __restrict__ B1,
                    const float* __restrict__ B2,
                    const float* __restrict__ b0, const float* __restrict__ b1,
                    const float* __restrict__ b2,
                    float* __restrict__ C0, float* __restrict__ C1,
                    float* __restrict__ C2,
                    int M, int N, int K)
{
    const float* B    = (blockIdx.z == 0) ? B0 : ((blockIdx.z == 1) ? B1 : B2);
    const float* bias = (blockIdx.z == 0) ? b0 : ((blockIdx.z == 1) ? b1 : b2);
    float*       C    = (blockIdx.z == 0) ? C0 : ((blockIdx.z == 1) ? C1 : C2);

    extern __shared__ float smg[];
    float* SAbase = smg;
    float* SBbase = smg + GSTAGES * ASZ;

    const int tid  = threadIdx.x;
    const int wid  = tid >> 5;
    const int lane = tid & 31;
    const int wm   = wid & 1;
    const int wn   = wid >> 1;
    const int gid  = lane >> 2;
    const int tig  = lane & 3;

    const float* Aptr = A + (long)blockIdx.y * GBM * K;
    const float* Bptr = B + blockIdx.x * GBN;

    const int arow = tid >> 3;
    const int ac   = (tid & 7) * 4;
    const int brow = tid >> 5;
    const int bc   = (tid & 31) * 4;

    float acc[4][4][4];
#pragma unroll
    for (int mi = 0; mi < 4; mi++)
#pragma unroll
        for (int ni = 0; ni < 4; ni++)
#pragma unroll
            for (int r = 0; r < 4; r++) acc[mi][ni][r] = 0.f;

    const int NT = K / GBK;

#define GEMM_ISSUE(KT, S)                                                     \
    do {                                                                      \
        float* as_ = SAbase + (S) * ASZ;                                      \
        float* bs_ = SBbase + (S) * BSZ;                                      \
        _Pragma("unroll")                                                     \
        for (int i_ = 0; i_ < 4; i_++) {                                      \
            int r_ = arow + i_ * 32;                                          \
            cp16(as_ + r_ * SAW + ac,                                         \
                 Aptr + (long)r_ * K + (KT) * GBK + ac);                      \
        }                                                                     \
        _Pragma("unroll")                                                     \
        for (int i_ = 0; i_ < 4; i_++) {                                      \
            int r_ = brow + i_ * 8;                                           \
            cp16(bs_ + r_ * SBW + bc,                                         \
                 Bptr + (long)((KT) * GBK + r_) * N + bc);                    \
        }                                                                     \
    } while (0)

#define LOAD_FRAGS(BUF, KB)                                                   \
    do {                                                                      \
        _Pragma("unroll")                                                     \
        for (int mi = 0; mi < 4; mi++) {                                      \
            int m = wm * 64 + mi * 16 + gid;                                  \
            af[BUF][mi][0] = asu[(m)     * SAW + (KB) + tig];                 \
            af[BUF][mi][1] = asu[(m + 8) * SAW + (KB) + tig];                 \
            af[BUF][mi][2] = asu[(m)     * SAW + (KB) + tig + 4];             \
            af[BUF][mi][3] = asu[(m + 8) * SAW + (KB) + tig + 4];             \
        }                                                                     \
        _Pragma("unroll")                                                     \
        for (int ni = 0; ni < 4; ni++) {                                      \
            int n = wn * 32 + ni * 8 + gid;                                   \
            bf[BUF][ni][0] = bsu[((KB) + tig)     * SBW + n];                 \
            bf[BUF][ni][1] = bsu[((KB) + tig + 4) * SBW + n];                 \
        }                                                                     \
    } while (0)

    GEMM_ISSUE(0, 0); cp_commit();
    GEMM_ISSUE(1, 1); cp_commit();

    for (int kt = 0; kt < NT; kt++) {
        const int s = kt % GSTAGES;
        if (kt + 2 < NT) cp_wait<1>(); else cp_wait<0>();
        __syncthreads();
        if (kt + 2 < NT) { GEMM_ISSUE(kt + 2, (kt + 2) % GSTAGES); cp_commit(); }

        const uint32_t* asu = (const uint32_t*)(SAbase + s * ASZ);
        const uint32_t* bsu = (const uint32_t*)(SBbase + s * BSZ);

        uint32_t af[2][4][4], bf[2][4][2];
        LOAD_FRAGS(0, 0);
#pragma unroll
        for (int ks = 0; ks < 4; ks++) {
            const int cur = ks & 1;
            if (ks < 3) {
                const int nxt = cur ^ 1;
                LOAD_FRAGS(nxt, (ks + 1) * 8);
            }
#pragma unroll
            for (int mi = 0; mi < 4; mi++)
#pragma unroll
                for (int ni = 0; ni < 4; ni++)
                    mma_tf32(acc[mi][ni], af[cur][mi], bf[cur][ni]);
        }
    }
#undef GEMM_ISSUE
#undef LOAD_FRAGS

    const int row_base = blockIdx.y * GBM + wm * 64;
    const int col_base = blockIdx.x * GBN + wn * 32;
#pragma unroll
    for (int mi = 0; mi < 4; mi++) {
#pragma unroll
        for (int ni = 0; ni < 4; ni++) {
            int r0 = row_base + mi * 16 + gid;
            int c  = col_base + ni * 8 + 2 * tig;
            float2 bv = *(const float2*)&bias[c];
            float2 o01, o23;
            o01.x = acc[mi][ni][0] + bv.x;
            o01.y = acc[mi][ni][1] + bv.y;
            o23.x = acc[mi][ni][2] + bv.x;
            o23.y = acc[mi][ni][3] + bv.y;
            if (ROUND_C) {
                o01.x = __uint_as_float(f2tf(o01.x));
                o01.y = __uint_as_float(f2tf(o01.y));
                o23.x = __uint_as_float(f2tf(o23.x));
                o23.y = __uint_as_float(f2tf(o23.y));
            }
            *(float2*)&C[(long)r0 * N + c]       = o01;
            *(float2*)&C[(long)(r0 + 8) * N + c] = o23;
        }
    }
}

// ---------------------------------------------------------------------------
// Tensor-core sliding-window flash attention, S-AHEAD PIPELINED:
// S(kt+1) is computed adjacent to softmax(kt) (independent -> ptxas can
// interleave MMA issue with the MUFU/shuffle chain). K and V buffers rotate
// separately: K(kt+2) issued right after the top barrier (Kbuf free once all
// warps passed S(kt)); V(kt+2) issued after PV(kt). Commit groups:
// {K0,V0}, {K1}, {V1}, then per iter {K(kt+2)}, {V(kt+2)}; loop-top
// cp_wait<1> (kt<hi) drains exactly K(kt+1)+V(kt); cp_wait<0> on last tile.
// All arithmetic values/order identical to R13 -> bit-identical output.
// ---------------------------------------------------------------------------
#define QT    64
#define ATHR  128
#define SQ_   68
#define SK_   68
#define SV_   72
#define KSZ   (64 * SK_)
#define VSZ   (64 * SV_)
#define ATT_SMEM_BYTES ((2 * QT * SQ_ + 2 * KSZ + 2 * VSZ) * 4)   // 106496

__global__ __launch_bounds__(ATHR, 2)
void attn_tc()
{
    extern __shared__ float sma[];
    uint32_t* Qs = (uint32_t*)sma;                 // [64][68] tf32 (scaled)
    uint32_t* Ps = Qs + QT * SQ_;                  // [64][68] tf32
    float*    Ks = sma + 2 * QT * SQ_;             // 2 x [64 key][68]
    float*    Vs = Ks + 2 * KSZ;                   // 2 x [64 key][72]

    const int h    = blockIdx.y;
    const int qt   = blockIdx.x;
    const int q0   = qt * QT;
    const int tid  = threadIdx.x;
    const int wid  = tid >> 5;                     // 0..3
    const int lane = tid & 31;
    const int gid  = lane >> 2;
    const int tig  = lane & 3;
    const int col  = h * HD;
    const int qw   = wid * 16;

    const int srow = tid >> 1;            // 0..63  (staging row = key)
    const int sc4  = (tid & 1) * 4;       // base col chunk; +8j covers row

    int kt_lo = qt - 4; if (kt_lo < 0) kt_lo = 0;
    const int kt_hi = qt;
    const bool multi = (kt_lo < kt_hi);

#define ISSUE_K(KT, S)                                                        \
    do {                                                                      \
        long gb_ = (long)((KT) * 64 + srow) * DM + col;                       \
        float* kd_ = Ks + (S) * KSZ + srow * SK_;                             \
        _Pragma("unroll")                                                     \
        for (int j_ = 0; j_ < 8; j_++) {                                      \
            int c_ = sc4 + 8 * j_;                                            \
            cp16(kd_ + c_, &g_k[gb_ + c_]);                                   \
        }                                                                     \
    } while (0)

#define ISSUE_V(KT, S)                                                        \
    do {                                                                      \
        long gb_ = (long)((KT) * 64 + srow) * DM + col;                       \
        float* vd_ = Vs + (S) * VSZ + srow * SV_;                             \
        _Pragma("unroll")                                                     \
        for (int j_ = 0; j_ < 8; j_++) {                                      \
            int c_ = sc4 + 8 * j_;                                            \
            cp16(vd_ + c_, &g_v[gb_ + c_]);                                   \
        }                                                                     \
    } while (0)

// S-tile MMA: dst[8][4] += Qs(rows of this warp) @ K^T from stage base ksb_.
#define COMPUTE_S(DST, KSB)                                                   \
    do {                                                                      \
        const uint32_t* ksb_ = (const uint32_t*)(KSB);                        \
        _Pragma("unroll")                                                     \
        for (int ni = 0; ni < 8; ni++)                                        \
            _Pragma("unroll")                                                 \
            for (int r = 0; r < 4; r++) (DST)[ni][r] = 0.f;                   \
        _Pragma("unroll")                                                     \
        for (int ksl = 0; ksl < 8; ksl++) {                                   \
            const int kb = ksl * 8;                                           \
            uint32_t a_[4];                                                   \
            a_[0] = Qs[prow0 + kb + tig];                                     \
            a_[1] = Qs[prow1 + kb + tig];                                     \
            a_[2] = Qs[prow0 + kb + tig + 4];                                 \
            a_[3] = Qs[prow1 + kb + tig + 4];                                 \
            uint32_t b_[8][2];                                                \
            _Pragma("unroll")                                                 \
            for (int ni = 0; ni < 8; ni++) {                                  \
                int n = ni * 8 + gid;                                         \
                b_[ni][0] = ksb_[n * SK_ + kb + tig];                         \
                b_[ni][1] = ksb_[n * SK_ + kb + tig + 4];                     \
            }                                                                 \
            _Pragma("unroll")                                                 \
            for (int ni = 0; ni < 8; ni++) mma_tf32((DST)[ni], a_, b_[ni]);   \
        }                                                                     \
    } while (0)

    // Prologue commits: G0={K(lo),V(lo)}, then G1a={K(lo+1)}, G1b={V(lo+1)}.
    ISSUE_K(kt_lo, 0); ISSUE_V(kt_lo, 0); cp_commit();
    if (multi) {
        ISSUE_K(kt_lo + 1, 1); cp_commit();
        ISSUE_V(kt_lo + 1, 1); cp_commit();
    }

    // Load + scale Q tile (overlaps with the in-flight K/V copies).
    for (int i = tid; i < QT * 16; i += ATHR) {
        int row = i >> 4;
        int c4  = (i & 15) * 4;
        float4 v = *(const float4*)&g_q[(long)(q0 + row) * DM + col + c4];
        uint32_t* dst = &Qs[row * SQ_ + c4];
        dst[0] = __float_as_uint(v.x * 0.125f);   // exact: q already tf32
        dst[1] = __float_as_uint(v.y * 0.125f);
        dst[2] = __float_as_uint(v.z * 0.125f);
        dst[3] = __float_as_uint(v.w * 0.125f);
    }

    const int prow0 = (qw + gid) * SQ_;
    const int prow1 = (qw + gid + 8) * SQ_;

    if (multi) cp_wait<2>(); else cp_wait<0>();   // G0 landed
    __syncthreads();                               // K/V(lo) + Qs visible

    float sr_cur[8][4], sr_next[8][4];
    COMPUTE_S(sr_cur, Ks + 0 * KSZ);

    float m0 = -1e30f, m1 = -1e30f, l0 = 0.f, l1 = 0.f;
    float o[8][4];
#pragma unroll
    for (int ni = 0; ni < 8; ni++)
#pragma unroll
        for (int r = 0; r < 4; r++) o[ni][r] = 0.f;

    for (int kt = kt_lo; kt <= kt_hi; kt++) {
        const int sk = (kt - kt_lo) & 1;

        // Drain K(kt+1)+V(kt) (keep youngest V(kt+1) in flight); barrier
        // also frees Kbuf[sk] (all warps past S(kt)).
        if (kt < kt_hi) cp_wait<1>(); else cp_wait<0>();
        __syncthreads();

        if (kt + 2 <= kt_hi) { ISSUE_K(kt + 2, sk); cp_commit(); }

        // S one tile ahead: independent of softmax(kt) below.
        if (kt < kt_hi) COMPUTE_S(sr_next, Ks + (sk ^ 1) * KSZ);

        // Mask + row stats on sr_cur (tile kt).
        const int iq0 = q0 + qw + gid;
        const int iq1 = iq0 + 8;
        float tmax0 = -1e30f, tmax1 = -1e30f;
#pragma unroll
        for (int ni = 0; ni < 8; ni++) {
            int jg = kt * 64 + ni * 8 + 2 * tig;
            bool k0, k1;
            k0 = (jg     <= iq0) && (iq0 - jg     < WIN);
            k1 = (jg + 1 <= iq0) && (iq0 - jg - 1 < WIN);
            sr_cur[ni][0] = k0 ? sr_cur[ni][0] : -1e30f;
            sr_cur[ni][1] = k1 ? sr_cur[ni][1] : -1e30f;
            k0 = (jg     <= iq1) && (iq1 - jg     < WIN);
            k1 = (jg + 1 <= iq1) && (iq1 - jg - 1 < WIN);
            sr_cur[ni][2] = k0 ? sr_cur[ni][2] : -1e30f;
            sr_cur[ni][3] = k1 ? sr_cur[ni][3] : -1e30f;
            tmax0 = fmaxf(tmax0, fmaxf(sr_cur[ni][0], sr_cur[ni][1]));
            tmax1 = fmaxf(tmax1, fmaxf(sr_cur[ni][2], sr_cur[ni][3]));
        }
        tmax0 = fmaxf(tmax0, __shfl_xor_sync(0xffffffffu, tmax0, 1));
        tmax0 = fmaxf(tmax0, __shfl_xor_sync(0xffffffffu, tmax0, 2));
        tmax1 = fmaxf(tmax1, __shfl_xor_sync(0xffffffffu, tmax1, 1));
        tmax1 = fmaxf(tmax1, __shfl_xor_sync(0xffffffffu, tmax1, 2));

        float mn0 = fmaxf(m0, tmax0), mn1 = fmaxf(m1, tmax1);
        float corr0 = __expf(m0 - mn0), corr1 = __expf(m1 - mn1);
        m0 = mn0; m1 = mn1;

        float ls0 = 0.f, ls1 = 0.f;
#pragma unroll
        for (int ni = 0; ni < 8; ni++) {
            int c = ni * 8 + 2 * tig;
            float p0 = (sr_cur[ni][0] > -1e29f) ? __expf(sr_cur[ni][0] - m0) : 0.f;
            float p1 = (sr_cur[ni][1] > -1e29f) ? __expf(sr_cur[ni][1] - m0) : 0.f;
            float p2 = (sr_cur[ni][2] > -1e29f) ? __expf(sr_cur[ni][2] - m1) : 0.f;
            float p3 = (sr_cur[ni][3] > -1e29f) ? __expf(sr_cur[ni][3] - m1) : 0.f;
            Ps[prow0 + c]     = f2tf(p0);
            Ps[prow0 + c + 1] = f2tf(p1);
            Ps[prow1 + c]     = f2tf(p2);
            Ps[prow1 + c + 1] = f2tf(p3);
            ls0 += p0 + p1;
            ls1 += p2 + p3;
        }
        ls0 += __shfl_xor_sync(0xffffffffu, ls0, 1);
        ls0 += __shfl_xor_sync(0xffffffffu, ls0, 2);
        ls1 += __shfl_xor_sync(0xffffffffu, ls1, 1);
        ls1 += __shfl_xor_sync(0xffffffffu, ls1, 2);
        l0 = l0 * corr0 + ls0;
        l1 = l1 * corr1 + ls1;
#pragma unroll
        for (int ni = 0; ni < 8; ni++) {
            o[ni][0] *= corr0; o[ni][1] *= corr0;
            o[ni][2] *= corr1; o[ni][3] *= corr1;
        }

        __syncwarp();   // Ps rows are per-warp private

        // O += P @ V  (V natural: element (k,n) at vs[k*SV_ + n])
        {
            const uint32_t* vs = (const uint32_t*)(Vs + sk * VSZ);
#pragma unroll
            for (int ksl = 0; ksl < 8; ksl++) {
                const int kb = ksl * 8;
                uint32_t a[4];
                a[0] = Ps[prow0 + kb + tig];
                a[1] = Ps[prow1 + kb + tig];
                a[2] = Ps[prow0 + kb + tig + 4];
                a[3] = Ps[prow1 + kb + tig + 4];
                uint32_t b[8][2];
#pragma unroll
                for (int ni = 0; ni < 8; ni++) {
                    int n = ni * 8 + gid;
                    b[ni][0] = vs[(kb + tig) * SV_ + n];
                    b[ni][1] = vs[(kb + tig + 4) * SV_ + n];
                }
#pragma unroll
                for (int ni = 0; ni < 8; ni++) mma_tf32(o[ni], a, b[ni]);
            }
        }

        __syncthreads();   // all warps done reading Vbuf[sk]
        if (kt + 2 <= kt_hi) { ISSUE_V(kt + 2, sk); cp_commit(); }

#pragma unroll
        for (int ni = 0; ni < 8; ni++)
#pragma unroll
            for (int r = 0; r < 4; r++) sr_cur[ni][r] = sr_next[ni][r];
    }
#undef ISSUE_K
#undef ISSUE_V
#undef COMPUTE_S

    // Epilogue: normalize, round to tf32 (consumer is the tf32 Wo GEMM).
    const float inv0 = 1.f / l0, inv1 = 1.f / l1;
    const int r0 = q0 + qw + gid;
#pragma unroll
    for (int ni = 0; ni < 8; ni++) {
        int c = col + ni * 8 + 2 * tig;
        float2 w0, w1;
        w0.x = __uint_as_float(f2tf(o[ni][0] * inv0));
        w0.y = __uint_as_float(f2tf(o[ni][1] * inv0));
        w1.x = __uint_as_float(f2tf(o[ni][2] * inv1));
        w1.y = __uint_as_float(f2tf(o[ni][3] * inv1));
        *(float2*)&g_att[(long)r0 * DM + c]       = w0;
        *(float2*)&g_att[(long)(r0 + 8) * DM + c] = w1;
    }
}

// ---------------------------------------------------------------------------
// Launch. Input order resolved at runtime from in_sizes (weights DM*DM,
// biases DM): grouped setup_inputs order or interleaved pair order.
// ---------------------------------------------------------------------------
extern "C" void kernel_launch(void* const* d_in, const int* in_sizes, int n_in,
                              void* d_out, int out_size)
{
    const float* x = (const float*)d_in[0];
    const float *Wq, *Wk, *Wv, *Wo, *bq, *bk, *bv, *bo;

    if (in_sizes[2] == DM) {
        Wq = (const float*)d_in[1]; bq = (const float*)d_in[2];
        Wk = (const float*)d_in[3]; bk = (const float*)d_in[4];
        Wv = (const float*)d_in[5]; bv = (const float*)d_in[6];
        Wo = (const float*)d_in[7]; bo = (const float*)d_in[8];
    } else {
        Wq = (const float*)d_in[1]; Wk = (const float*)d_in[2];
        Wv = (const float*)d_in[3]; Wo = (const float*)d_in[4];
        bq = (const float*)d_in[5]; bk = (const float*)d_in[6];
        bv = (const float*)d_in[7]; bo = (const float*)d_in[8];
    }
    float* out = (float*)d_out;

    float *q, *k, *v, *att, *xtf, *wtf;
    cudaGetSymbolAddress((void**)&q,   g_q);
    cudaGetSymbolAddress((void**)&k,   g_k);
    cudaGetSymbolAddress((void**)&v,   g_v);
    cudaGetSymbolAddress((void**)&att, g_att);
    cudaGetSymbolAddress((void**)&xtf, g_xtf);
    cudaGetSymbolAddress((void**)&wtf, g_wtf);

    cudaFuncSetAttribute(gemm_tf32_bias<true>,
                         cudaFuncAttributeMaxDynamicSharedMemorySize,
                         GEMM_SMEM_BYTES);
    cudaFuncSetAttribute(gemm_tf32_bias<false>,
                         cudaFuncAttributeMaxDynamicSharedMemorySize,
                         GEMM_SMEM_BYTES);
    cudaFuncSetAttribute(attn_tc,
                         cudaFuncAttributeMaxDynamicSharedMemorySize,
                         ATT_SMEM_BYTES);

    // Pre-round x and weights to tf32 (bit-identical to mainloop cvt.rna).
    round_x_kernel<<<SEQ * DM / 4 / 256, 256>>>(x, xtf);
    dim3 gw(DM * DM / 4 / 256, 1, 4);
    round_w_kernel<<<gw, 256>>>(Wq, Wk, Wv, Wo, wtf);

    const float* wq = wtf;
    const float* wk = wtf + (size_t)DM * DM;
    const float* wv = wtf + (size_t)2 * DM * DM;
    const float* wo = wtf + (size_t)3 * DM * DM;

    dim3 gqkv(DM / GBN, SEQ / GBM, 3);
    gemm_tf32_bias<true><<<gqkv, 256, GEMM_SMEM_BYTES>>>(
        xtf, wq, wk, wv, bq, bk, bv, q, k, v, SEQ, DM, DM);

    dim3 gat(SEQ / QT, NH);
    attn_tc<<<gat, ATHR, ATT_SMEM_BYTES>>>();

    dim3 gout(DM / GBN, SEQ / GBM, 1);
    gemm_tf32_bias<false><<<gout, 256, GEMM_SMEM_BYTES>>>(
        att, wo, wo, wo, bo, bo, bo, out, out, out, SEQ, DM, DM);
}

// round 16
// speedup vs baseline: 1.3181x; 1.0541x over previous
#include <cuda_runtime.h>
#include <cstdint>

#define SEQ   4096
#define DM    1024
#define NH    16
#define HD    64
#define WIN   256

// Scratch (allocation-free: __device__ globals)
__device__ float g_q[SEQ * DM];
__device__ float g_k[SEQ * DM];
__device__ float g_v[SEQ * DM];
__device__ float g_att[SEQ * DM];
__device__ float g_xtf[SEQ * DM];        // x pre-rounded to tf32
__device__ float g_wtf[4 * DM * DM];     // Wq,Wk,Wv,Wo pre-rounded to tf32

// ---------------------------------------------------------------------------
// Common helpers
// ---------------------------------------------------------------------------
__device__ __forceinline__ uint32_t f2tf(float f) {
    uint32_t u;
    asm("cvt.rna.tf32.f32 %0, %1;" : "=r"(u) : "f"(f));
    return u;
}

__device__ __forceinline__ void mma_tf32(float (&d)[4],
                                         const uint32_t (&a)[4],
                                         const uint32_t (&b)[2]) {
    asm volatile(
        "mma.sync.aligned.m16n8k8.row.col.f32.tf32.tf32.f32 "
        "{%0,%1,%2,%3}, {%4,%5,%6,%7}, {%8,%9}, {%0,%1,%2,%3};\n"
        : "+f"(d[0]), "+f"(d[1]), "+f"(d[2]), "+f"(d[3])
        : "r"(a[0]), "r"(a[1]), "r"(a[2]), "r"(a[3]),
          "r"(b[0]), "r"(b[1]));
}

__device__ __forceinline__ void cp16(void* sdst, const float* gsrc) {
    uint32_t s = (uint32_t)__cvta_generic_to_shared(sdst);
    asm volatile("cp.async.cg.shared.global [%0], [%1], 16;\n"
                 :: "r"(s), "l"(gsrc));
}
__device__ __forceinline__ void cp_commit() {
    asm volatile("cp.async.commit_group;\n");
}
template <int N> __device__ __forceinline__ void cp_wait() {
    asm volatile("cp.async.wait_group %0;\n" :: "n"(N));
}

// ---------------------------------------------------------------------------
// Merged tf32 pre-rounding: x + 4 weights in ONE launch.
// Grid covers (SEQ*DM + 4*DM*DM)/4 float4 elements.
// ---------------------------------------------------------------------------
__global__ __launch_bounds__(256)
void round_all_kernel(const float* __restrict__ x,
                      const float* __restrict__ W0, const float* __restrict__ W1,
                      const float* __restrict__ W2, const float* __restrict__ W3,
                      float* __restrict__ xd, float* __restrict__ wd)
{
    long i4 = (long)blockIdx.x * 256 + threadIdx.x;
    const long nx4 = (long)SEQ * DM / 4;
    const long nw4 = (long)DM * DM / 4;
    const float* src;
    float* dst;
    long j;
    if (i4 < nx4) {
        src = x; dst = xd; j = i4;
    } else {
        long t = i4 - nx4;
        int w = (int)(t / nw4);
        j = t - (long)w * nw4;
        src = (w == 0) ? W0 : (w == 1) ? W1 : (w == 2) ? W2 : W3;
        dst = wd + (long)w * DM * DM;
    }
    float4 v = ((const float4*)src)[j];
    uint4 u;
    u.x = f2tf(v.x); u.y = f2tf(v.y); u.z = f2tf(v.z); u.w = f2tf(v.w);
    ((uint4*)dst)[j] = u;
}

// ---------------------------------------------------------------------------
// tf32 tensor-core GEMM with bias, 3-stage cp.async pipeline.
// FROZEN at the R13-verified configuration (GBK=32, 2 CTAs/SM).
// ---------------------------------------------------------------------------
#define GBM 128
#define GBN 128
#define GBK 32
#define SAW 36
#define SBW 136
#define ASZ (GBM * SAW)
#define BSZ (GBK * SBW)
#define GSTAGES 3
#define GEMM_SMEM_BYTES (GSTAGES * (ASZ + BSZ) * 4)   // 107520

template <bool ROUND_C>
__global__ __launch_bounds__(256, 2)
void gemm_tf32_bias(const float* __restrict__ A,
                    const float* __restrict__ B0, const float* __restrict__ B1,
                    const float* __restrict__ B2,
                    const float* __restrict__ b0, const float* __restrict__ b1,
                    const float* __restrict__ b2,
                    float* __restrict__ C0, float* __restrict__ C1,
                    float* __restrict__ C2,
                    int M, int N, int K)
{
    const float* B    = (blockIdx.z == 0) ? B0 : ((blockIdx.z == 1) ? B1 : B2);
    const float* bias = (blockIdx.z == 0) ? b0 : ((blockIdx.z == 1) ? b1 : b2);
    float*       C    = (blockIdx.z == 0) ? C0 : ((blockIdx.z == 1) ? C1 : C2);

    extern __shared__ float smg[];
    float* SAbase = smg;
    float* SBbase = smg + GSTAGES * ASZ;

    const int tid  = threadIdx.x;
    const int wid  = tid >> 5;
    const int lane = tid & 31;
    const int wm   = wid & 1;
    const int wn   = wid >> 1;
    const int gid  = lane >> 2;
    const int tig  = lane & 3;

    const float* Aptr = A + (long)blockIdx.y * GBM * K;
    const float* Bptr = B + blockIdx.x * GBN;

    const int arow = tid >> 3;
    const int ac   = (tid & 7) * 4;
    const int brow = tid >> 5;
    const int bc   = (tid & 31) * 4;

    float acc[4][4][4];
#pragma unroll
    for (int mi = 0; mi < 4; mi++)
#pragma unroll
        for (int ni = 0; ni < 4; ni++)
#pragma unroll
            for (int r = 0; r < 4; r++) acc[mi][ni][r] = 0.f;

    const int NT = K / GBK;

#define GEMM_ISSUE(KT, S)                                                     \
    do {                                                                      \
        float* as_ = SAbase + (S) * ASZ;                                      \
        float* bs_ = SBbase + (S) * BSZ;                                      \
        _Pragma("unroll")                                                     \
        for (int i_ = 0; i_ < 4; i_++) {                                      \
            int r_ = arow + i_ * 32;                                          \
            cp16(as_ + r_ * SAW + ac,                                         \
                 Aptr + (long)r_ * K + (KT) * GBK + ac);                      \
        }                                                                     \
        _Pragma("unroll")                                                     \
        for (int i_ = 0; i_ < 4; i_++) {                                      \
            int r_ = brow + i_ * 8;                                           \
            cp16(bs_ + r_ * SBW + bc,                                         \
                 Bptr + (long)((KT) * GBK + r_) * N + bc);                    \
        }                                                                     \
    } while (0)

#define LOAD_FRAGS(BUF, KB)                                                   \
    do {                                                                      \
        _Pragma("unroll")                                                     \
        for (int mi = 0; mi < 4; mi++) {                                      \
            int m = wm * 64 + mi * 16 + gid;                                  \
            af[BUF][mi][0] = asu[(m)     * SAW + (KB) + tig];                 \
            af[BUF][mi][1] = asu[(m + 8) * SAW + (KB) + tig];                 \
            af[BUF][mi][2] = asu[(m)     * SAW + (KB) + tig + 4];             \
            af[BUF][mi][3] = asu[(m + 8) * SAW + (KB) + tig + 4];             \
        }                                                                     \
        _Pragma("unroll")                                                     \
        for (int ni = 0; ni < 4; ni++) {                                      \
            int n = wn * 32 + ni * 8 + gid;                                   \
            bf[BUF][ni][0] = bsu[((KB) + tig)     * SBW + n];                 \
            bf[BUF][ni][1] = bsu[((KB) + tig + 4) * SBW + n];                 \
        }                                                                     \
    } while (0)

    GEMM_ISSUE(0, 0); cp_commit();
    GEMM_ISSUE(1, 1); cp_commit();

    for (int kt = 0; kt < NT; kt++) {
        const int s = kt % GSTAGES;
        if (kt + 2 < NT) cp_wait<1>(); else cp_wait<0>();
        __syncthreads();
        if (kt + 2 < NT) { GEMM_ISSUE(kt + 2, (kt + 2) % GSTAGES); cp_commit(); }

        const uint32_t* asu = (const uint32_t*)(SAbase + s * ASZ);
        const uint32_t* bsu = (const uint32_t*)(SBbase + s * BSZ);

        uint32_t af[2][4][4], bf[2][4][2];
        LOAD_FRAGS(0, 0);
#pragma unroll
        for (int ks = 0; ks < 4; ks++) {
            const int cur = ks & 1;
            if (ks < 3) {
                const int nxt = cur ^ 1;
                LOAD_FRAGS(nxt, (ks + 1) * 8);
            }
#pragma unroll
            for (int mi = 0; mi < 4; mi++)
#pragma unroll
                for (int ni = 0; ni < 4; ni++)
                    mma_tf32(acc[mi][ni], af[cur][mi], bf[cur][ni]);
        }
    }
#undef GEMM_ISSUE
#undef LOAD_FRAGS

    const int row_base = blockIdx.y * GBM + wm * 64;
    const int col_base = blockIdx.x * GBN + wn * 32;
#pragma unroll
    for (int mi = 0; mi < 4; mi++) {
#pragma unroll
        for (int ni = 0; ni < 4; ni++) {
            int r0 = row_base + mi * 16 + gid;
            int c  = col_base + ni * 8 + 2 * tig;
            float2 bv = *(const float2*)&bias[c];
            float2 o01, o23;
            o01.x = acc[mi][ni][0] + bv.x;
            o01.y = acc[mi][ni][1] + bv.y;
            o23.x = acc[mi][ni][2] + bv.x;
            o23.y = acc[mi][ni][3] + bv.y;
            if (ROUND_C) {
                o01.x = __uint_as_float(f2tf(o01.x));
                o01.y = __uint_as_float(f2tf(o01.y));
                o23.x = __uint_as_float(f2tf(o23.x));
                o23.y = __uint_as_float(f2tf(o23.y));
            }
            *(float2*)&C[(long)r0 * N + c]       = o01;
            *(float2*)&C[(long)(r0 + 8) * N + c] = o23;
        }
    }
}

// ---------------------------------------------------------------------------
// Tensor-core sliding-window flash attention, Q-IN-REGISTERS:
// Q a-fragments are tile-invariant, so each thread LDGs its 32 Q elements
// once (values bit-identical: g_q is tf32, *2^-3 exact) -- removes the Qs
// smem buffer and 32 LDS per warp per tile from the S phase. Everything
// else keeps the R15 S-ahead structure: K/V rotate separately, commit
// groups {K0,V0},{K1},{V1}, per-iter {K(kt+2)} then {V(kt+2)};
// loop-top cp_wait<1> drains K(kt+1)+V(kt). smem 89KB -> 2 CTAs/SM.
// All arithmetic values/order identical -> bit-identical output.
// ---------------------------------------------------------------------------
#define QT    64
#define ATHR  128
#define SQ_   68
#define SK_   68
#define SV_   72
#define KSZ   (64 * SK_)
#define VSZ   (64 * SV_)
#define ATT_SMEM_BYTES ((QT * SQ_ + 2 * KSZ + 2 * VSZ) * 4)   // 89088

__global__ __launch_bounds__(ATHR, 2)
void attn_tc()
{
    extern __shared__ float sma[];
    uint32_t* Ps = (uint32_t*)sma;                 // [64][68] tf32
    float*    Ks = sma + QT * SQ_;                 // 2 x [64 key][68]
    float*    Vs = Ks + 2 * KSZ;                   // 2 x [64 key][72]

    const int h    = blockIdx.y;
    const int qt   = blockIdx.x;
    const int q0   = qt * QT;
    const int tid  = threadIdx.x;
    const int wid  = tid >> 5;                     // 0..3
    const int lane = tid & 31;
    const int gid  = lane >> 2;
    const int tig  = lane & 3;
    const int col  = h * HD;
    const int qw   = wid * 16;

    const int srow = tid >> 1;            // 0..63  (staging row = key)
    const int sc4  = (tid & 1) * 4;       // base col chunk; +8j covers row

    int kt_lo = qt - 4; if (kt_lo < 0) kt_lo = 0;
    const int kt_hi = qt;
    const bool multi = (kt_lo < kt_hi);

#define ISSUE_K(KT, S)                                                        \
    do {                                                                      \
        long gb_ = (long)((KT) * 64 + srow) * DM + col;                       \
        float* kd_ = Ks + (S) * KSZ + srow * SK_;                             \
        _Pragma("unroll")                                                     \
        for (int j_ = 0; j_ < 8; j_++) {                                      \
            int c_ = sc4 + 8 * j_;                                            \
            cp16(kd_ + c_, &g_k[gb_ + c_]);                                   \
        }                                                                     \
    } while (0)

#define ISSUE_V(KT, S)                                                        \
    do {                                                                      \
        long gb_ = (long)((KT) * 64 + srow) * DM + col;                       \
        float* vd_ = Vs + (S) * VSZ + srow * SV_;                             \
        _Pragma("unroll")                                                     \
        for (int j_ = 0; j_ < 8; j_++) {                                      \
            int c_ = sc4 + 8 * j_;                                            \
            cp16(vd_ + c_, &g_v[gb_ + c_]);                                   \
        }                                                                     \
    } while (0)

// S-tile MMA from register-resident Q fragments and stage base KSB.
#define COMPUTE_S(DST, KSB)                                                   \
    do {                                                                      \
        const uint32_t* ksb_ = (const uint32_t*)(KSB);                        \
        _Pragma("unroll")                                                     \
        for (int ni = 0; ni < 8; ni++)                                        \
            _Pragma("unroll")                                                 \
            for (int r = 0; r < 4; r++) (DST)[ni][r] = 0.f;                   \
        _Pragma("unroll")                                                     \
        for (int ksl = 0; ksl < 8; ksl++) {                                   \
            const int kb = ksl * 8;                                           \
            uint32_t b_[8][2];                                                \
            _Pragma("unroll")                                                 \
            for (int ni = 0; ni < 8; ni++) {                                  \
                int n = ni * 8 + gid;                                         \
                b_[ni][0] = ksb_[n * SK_ + kb + tig];                         \
                b_[ni][1] = ksb_[n * SK_ + kb + tig + 4];                     \
            }                                                                 \
            _Pragma("unroll")                                                 \
            for (int ni = 0; ni < 8; ni++) mma_tf32((DST)[ni], aq[ksl], b_[ni]); \
        }                                                                     \
    } while (0)

    // Prologue commits: G0={K(lo),V(lo)}, then G1a={K(lo+1)}, G1b={V(lo+1)}.
    ISSUE_K(kt_lo, 0); ISSUE_V(kt_lo, 0); cp_commit();
    if (multi) {
        ISSUE_K(kt_lo + 1, 1); cp_commit();
        ISSUE_V(kt_lo + 1, 1); cp_commit();
    }

    // Q a-fragments direct from GMEM (overlaps in-flight K/V copies).
    // Values identical to the former smem path: g_q tf32, *0.125 exact.
    uint32_t aq[8][4];
    {
        const float* qrow0 = &g_q[(long)(q0 + qw + gid) * DM + col];
        const float* qrow1 = qrow0 + 8 * DM;
#pragma unroll
        for (int ksl = 0; ksl < 8; ksl++) {
            const int kb = ksl * 8;
            aq[ksl][0] = __float_as_uint(qrow0[kb + tig]     * 0.125f);
            aq[ksl][1] = __float_as_uint(qrow1[kb + tig]     * 0.125f);
            aq[ksl][2] = __float_as_uint(qrow0[kb + tig + 4] * 0.125f);
            aq[ksl][3] = __float_as_uint(qrow1[kb + tig + 4] * 0.125f);
        }
    }

    const int prow0 = (qw + gid) * SQ_;
    const int prow1 = (qw + gid + 8) * SQ_;

    if (multi) cp_wait<2>(); else cp_wait<0>();   // G0 landed
    __syncthreads();                               // K/V(lo) visible

    float sr_cur[8][4], sr_next[8][4];
    COMPUTE_S(sr_cur, Ks + 0 * KSZ);

    float m0 = -1e30f, m1 = -1e30f, l0 = 0.f, l1 = 0.f;
    float o[8][4];
#pragma unroll
    for (int ni = 0; ni < 8; ni++)
#pragma unroll
        for (int r = 0; r < 4; r++) o[ni][r] = 0.f;

    for (int kt = kt_lo; kt <= kt_hi; kt++) {
        const int sk = (kt - kt_lo) & 1;

        // Drain K(kt+1)+V(kt) (keep youngest V(kt+1) in flight); barrier
        // also frees Kbuf[sk] (all warps past S(kt)).
        if (kt < kt_hi) cp_wait<1>(); else cp_wait<0>();
        __syncthreads();

        if (kt + 2 <= kt_hi) { ISSUE_K(kt + 2, sk); cp_commit(); }

        // S one tile ahead: independent of softmax(kt) below.
        if (kt < kt_hi) COMPUTE_S(sr_next, Ks + (sk ^ 1) * KSZ);

        // Mask + row stats on sr_cur (tile kt).
        const int iq0 = q0 + qw + gid;
        const int iq1 = iq0 + 8;
        float tmax0 = -1e30f, tmax1 = -1e30f;
#pragma unroll
        for (int ni = 0; ni < 8; ni++) {
            int jg = kt * 64 + ni * 8 + 2 * tig;
            bool k0, k1;
            k0 = (jg     <= iq0) && (iq0 - jg     < WIN);
            k1 = (jg + 1 <= iq0) && (iq0 - jg - 1 < WIN);
            sr_cur[ni][0] = k0 ? sr_cur[ni][0] : -1e30f;
            sr_cur[ni][1] = k1 ? sr_cur[ni][1] : -1e30f;
            k0 = (jg     <= iq1) && (iq1 - jg     < WIN);
            k1 = (jg + 1 <= iq1) && (iq1 - jg - 1 < WIN);
            sr_cur[ni][2] = k0 ? sr_cur[ni][2] : -1e30f;
            sr_cur[ni][3] = k1 ? sr_cur[ni][3] : -1e30f;
            tmax0 = fmaxf(tmax0, fmaxf(sr_cur[ni][0], sr_cur[ni][1]));
            tmax1 = fmaxf(tmax1, fmaxf(sr_cur[ni][2], sr_cur[ni][3]));
        }
        tmax0 = fmaxf(tmax0, __shfl_xor_sync(0xffffffffu, tmax0, 1));
        tmax0 = fmaxf(tmax0, __shfl_xor_sync(0xffffffffu, tmax0, 2));
        tmax1 = fmaxf(tmax1, __shfl_xor_sync(0xffffffffu, tmax1, 1));
        tmax1 = fmaxf(tmax1, __shfl_xor_sync(0xffffffffu, tmax1, 2));

        float mn0 = fmaxf(m0, tmax0), mn1 = fmaxf(m1, tmax1);
        float corr0 = __expf(m0 - mn0), corr1 = __expf(m1 - mn1);
        m0 = mn0; m1 = mn1;

        float ls0 = 0.f, ls1 = 0.f;
#pragma unroll
        for (int ni = 0; ni < 8; ni++) {
            int c = ni * 8 + 2 * tig;
            float p0 = (sr_cur[ni][0] > -1e29f) ? __expf(sr_cur[ni][0] - m0) : 0.f;
            float p1 = (sr_cur[ni][1] > -1e29f) ? __expf(sr_cur[ni][1] - m0) : 0.f;
            float p2 = (sr_cur[ni][2] > -1e29f) ? __expf(sr_cur[ni][2] - m1) : 0.f;
            float p3 = (sr_cur[ni][3] > -1e29f) ? __expf(sr_cur[ni][3] - m1) : 0.f;
            Ps[prow0 + c]     = f2tf(p0);
            Ps[prow0 + c + 1] = f2tf(p1);
            Ps[prow1 + c]     = f2tf(p2);
            Ps[prow1 + c + 1] = f2tf(p3);
            ls0 += p0 + p1;
            ls1 += p2 + p3;
        }
        ls0 += __shfl_xor_sync(0xffffffffu, ls0, 1);
        ls0 += __shfl_xor_sync(0xffffffffu, ls0, 2);
        ls1 += __shfl_xor_sync(0xffffffffu, ls1, 1);
        ls1 += __shfl_xor_sync(0xffffffffu, ls1, 2);
        l0 = l0 * corr0 + ls0;
        l1 = l1 * corr1 + ls1;
#pragma unroll
        for (int ni = 0; ni < 8; ni++) {
            o[ni][0] *= corr0; o[ni][1] *= corr0;
            o[ni][2] *= corr1; o[ni][3] *= corr1;
        }

        __syncwarp();   // Ps rows are per-warp private

        // O += P @ V  (V natural: element (k,n) at vs[k*SV_ + n])
        {
            const uint32_t* vs = (const uint32_t*)(Vs + sk * VSZ);
#pragma unroll
            for (int ksl = 0; ksl < 8; ksl++) {
                const int kb = ksl * 8;
                uint32_t a[4];
                a[0] = Ps[prow0 + kb + tig];
                a[1] = Ps[prow1 + kb + tig];
                a[2] = Ps[prow0 + kb + tig + 4];
                a[3] = Ps[prow1 + kb + tig + 4];
                uint32_t b[8][2];
#pragma unroll
                for (int ni = 0; ni < 8; ni++) {
                    int n = ni * 8 + gid;
                    b[ni][0] = vs[(kb + tig) * SV_ + n];
                    b[ni][1] = vs[(kb + tig + 4) * SV_ + n];
                }
#pragma unroll
                for (int ni = 0; ni < 8; ni++) mma_tf32(o[ni], a, b[ni]);
            }
        }

        __syncthreads();   // all warps done reading Vbuf[sk]
        if (kt + 2 <= kt_hi) { ISSUE_V(kt + 2, sk); cp_commit(); }

#pragma unroll
        for (int ni = 0; ni < 8; ni++)
#pragma unroll
            for (int r = 0; r < 4; r++) sr_cur[ni][r] = sr_next[ni][r];
    }
#undef ISSUE_K
#undef ISSUE_V
#undef COMPUTE_S

    // Epilogue: normalize, round to tf32 (consumer is the tf32 Wo GEMM).
    const float inv0 = 1.f / l0, inv1 = 1.f / l1;
    const int r0 = q0 + qw + gid;
#pragma unroll
    for (int ni = 0; ni < 8; ni++) {
        int c = col + ni * 8 + 2 * tig;
        float2 w0, w1;
        w0.x = __uint_as_float(f2tf(o[ni][0] * inv0));
        w0.y = __uint_as_float(f2tf(o[ni][1] * inv0));
        w1.x = __uint_as_float(f2tf(o[ni][2] * inv1));
        w1.y = __uint_as_float(f2tf(o[ni][3] * inv1));
        *(float2*)&g_att[(long)r0 * DM + c]       = w0;
        *(float2*)&g_att[(long)(r0 + 8) * DM + c] = w1;
    }
}

// ---------------------------------------------------------------------------
// Launch. Input order resolved at runtime from in_sizes (weights DM*DM,
// biases DM): grouped setup_inputs order or interleaved pair order.
// ---------------------------------------------------------------------------
extern "C" void kernel_launch(void* const* d_in, const int* in_sizes, int n_in,
                              void* d_out, int out_size)
{
    const float* x = (const float*)d_in[0];
    const float *Wq, *Wk, *Wv, *Wo, *bq, *bk, *bv, *bo;

    if (in_sizes[2] == DM) {
        Wq = (const float*)d_in[1]; bq = (const float*)d_in[2];
        Wk = (const float*)d_in[3]; bk = (const float*)d_in[4];
        Wv = (const float*)d_in[5]; bv = (const float*)d_in[6];
        Wo = (const float*)d_in[7]; bo = (const float*)d_in[8];
    } else {
        Wq = (const float*)d_in[1]; Wk = (const float*)d_in[2];
        Wv = (const float*)d_in[3]; Wo = (const float*)d_in[4];
        bq = (const float*)d_in[5]; bk = (const float*)d_in[6];
        bv = (const float*)d_in[7]; bo = (const float*)d_in[8];
    }
    float* out = (float*)d_out;

    float *q, *k, *v, *att, *xtf, *wtf;
    cudaGetSymbolAddress((void**)&q,   g_q);
    cudaGetSymbolAddress((void**)&k,   g_k);
    cudaGetSymbolAddress((void**)&v,   g_v);
    cudaGetSymbolAddress((void**)&att, g_att);
    cudaGetSymbolAddress((void**)&xtf, g_xtf);
    cudaGetSymbolAddress((void**)&wtf, g_wtf);

    cudaFuncSetAttribute(gemm_tf32_bias<true>,
                         cudaFuncAttributeMaxDynamicSharedMemorySize,
                         GEMM_SMEM_BYTES);
    cudaFuncSetAttribute(gemm_tf32_bias<false>,
                         cudaFuncAttributeMaxDynamicSharedMemorySize,
                         GEMM_SMEM_BYTES);
    cudaFuncSetAttribute(attn_tc,
                         cudaFuncAttributeMaxDynamicSharedMemorySize,
                         ATT_SMEM_BYTES);

    // One merged pre-round launch: x + all 4 weights.
    const int nblk = (SEQ * DM + 4 * DM * DM) / 4 / 256;   // 8192
    round_all_kernel<<<nblk, 256>>>(x, Wq, Wk, Wv, Wo, xtf, wtf);

    const float* wq = wtf;
    const float* wk = wtf + (size_t)DM * DM;
    const float* wv = wtf + (size_t)2 * DM * DM;
    const float* wo = wtf + (size_t)3 * DM * DM;

    dim3 gqkv(DM / GBN, SEQ / GBM, 3);
    gemm_tf32_bias<true><<<gqkv, 256, GEMM_SMEM_BYTES>>>(
        xtf, wq, wk, wv, bq, bk, bv, q, k, v, SEQ, DM, DM);

    dim3 gat(SEQ / QT, NH);
    attn_tc<<<gat, ATHR, ATT_SMEM_BYTES>>>();

    dim3 gout(DM / GBN, SEQ / GBM, 1);
    gemm_tf32_bias<false><<<gout, 256, GEMM_SMEM_BYTES>>>(
        att, wo, wo, wo, bo, bo, bo, out, out, out, SEQ, DM, DM);
}

// round 17
// speedup vs baseline: 1.3200x; 1.0014x over previous
#include <cuda_runtime.h>
#include <cstdint>

#define SEQ   4096
#define DM    1024
#define NH    16
#define HD    64
#define WIN   256

// Scratch (allocation-free: __device__ globals)
__device__ float g_q[SEQ * DM];
__device__ float g_k[SEQ * DM];
__device__ float g_v[SEQ * DM];
__device__ float g_att[SEQ * DM];
__device__ float g_xtf[SEQ * DM];        // x pre-rounded to tf32
__device__ float g_wtf[4 * DM * DM];     // W^T (q,k,v,o) pre-rounded to tf32

// ---------------------------------------------------------------------------
// Common helpers
// ---------------------------------------------------------------------------
__device__ __forceinline__ uint32_t f2tf(float f) {
    uint32_t u;
    asm("cvt.rna.tf32.f32 %0, %1;" : "=r"(u) : "f"(f));
    return u;
}

__device__ __forceinline__ void mma_tf32(float (&d)[4],
                                         const uint32_t (&a)[4],
                                         const uint32_t (&b)[2]) {
    asm volatile(
        "mma.sync.aligned.m16n8k8.row.col.f32.tf32.tf32.f32 "
        "{%0,%1,%2,%3}, {%4,%5,%6,%7}, {%8,%9}, {%0,%1,%2,%3};\n"
        : "+f"(d[0]), "+f"(d[1]), "+f"(d[2]), "+f"(d[3])
        : "r"(a[0]), "r"(a[1]), "r"(a[2]), "r"(a[3]),
          "r"(b[0]), "r"(b[1]));
}

__device__ __forceinline__ void ldm_x4(uint32_t (&r)[4], uint32_t addr) {
    asm volatile("ldmatrix.sync.aligned.m8n8.x4.shared.b16 {%0,%1,%2,%3}, [%4];"
                 : "=r"(r[0]), "=r"(r[1]), "=r"(r[2]), "=r"(r[3]) : "r"(addr));
}
__device__ __forceinline__ void ldm_x2(uint32_t (&r)[2], uint32_t addr) {
    asm volatile("ldmatrix.sync.aligned.m8n8.x2.shared.b16 {%0,%1}, [%2];"
                 : "=r"(r[0]), "=r"(r[1]) : "r"(addr));
}

__device__ __forceinline__ void cp16(void* sdst, const float* gsrc) {
    uint32_t s = (uint32_t)__cvta_generic_to_shared(sdst);
    asm volatile("cp.async.cg.shared.global [%0], [%1], 16;\n"
                 :: "r"(s), "l"(gsrc));
}
__device__ __forceinline__ void cp_commit() {
    asm volatile("cp.async.commit_group;\n");
}
template <int N> __device__ __forceinline__ void cp_wait() {
    asm volatile("cp.async.wait_group %0;\n" :: "n"(N));
}

// ---------------------------------------------------------------------------
// Pre-rounding: x flat; weights TRANSPOSED (for n-major B staging -> ldmatrix).
// ---------------------------------------------------------------------------
__global__ __launch_bounds__(256)
void round_x_kernel(const float* __restrict__ src, float* __restrict__ dst)
{
    int i = blockIdx.x * 256 + threadIdx.x;   // n4 = SEQ*DM/4
    float4 v = ((const float4*)src)[i];
    uint4 w;
    w.x = f2tf(v.x); w.y = f2tf(v.y); w.z = f2tf(v.z); w.w = f2tf(v.w);
    ((uint4*)dst)[i] = w;
}

// dst[z][n][k] = rnd(W[k][n]) -- tiled transpose + tf32 round.
__global__ __launch_bounds__(256)
void roundT_w_kernel(const float* __restrict__ W0, const float* __restrict__ W1,
                     const float* __restrict__ W2, const float* __restrict__ W3,
                     float* __restrict__ dst)
{
    __shared__ float t[32][33];
    const float* W = (blockIdx.z == 0) ? W0 : (blockIdx.z == 1) ? W1
                   : (blockIdx.z == 2) ? W2 : W3;
    float* D = dst + (size_t)blockIdx.z * DM * DM;
    const int bx = blockIdx.x * 32;   // k block
    const int by = blockIdx.y * 32;   // n block
    const int tx = threadIdx.x & 31;
    const int ty = threadIdx.x >> 5;
#pragma unroll
    for (int j = 0; j < 4; j++)
        t[ty + j * 8][tx] = W[(long)(bx + ty + j * 8) * DM + by + tx];
    __syncthreads();
#pragma unroll
    for (int j = 0; j < 4; j++)
        D[(long)(by + ty + j * 8) * DM + bx + tx] =
            __uint_as_float(f2tf(t[tx][ty + j * 8]));
}

// ---------------------------------------------------------------------------
// tf32 tensor-core GEMM with bias, 3-stage cp.async pipeline, LDMATRIX
// fragment loads. C = A[M,K] @ W[K,N] + bias, with W supplied TRANSPOSED
// (rows = n). SMEM: A [128 m][36 k], B [128 n][36 k] (both 16B-aligned rows).
// Fragment values and MMA order identical to the verified scalar-LDS kernel.
// ---------------------------------------------------------------------------
#define GBM 128
#define GBN 128
#define GBK 32
#define SAW 36
#define SBW 36
#define ASZ (GBM * SAW)
#define BSZ (GBN * SBW)
#define GSTAGES 3
#define GEMM_SMEM_BYTES (GSTAGES * (ASZ + BSZ) * 4)   // 110592

template <bool ROUND_C>
__global__ __launch_bounds__(256, 2)
void gemm_tf32_bias(const float* __restrict__ A,
                    const float* __restrict__ B0, const float* __restrict__ B1,
                    const float* __restrict__ B2,
                    const float* __restrict__ b0, const float* __restrict__ b1,
                    const float* __restrict__ b2,
                    float* __restrict__ C0, float* __restrict__ C1,
                    float* __restrict__ C2,
                    int M, int N, int K)
{
    const float* BT   = (blockIdx.z == 0) ? B0 : ((blockIdx.z == 1) ? B1 : B2);
    const float* bias = (blockIdx.z == 0) ? b0 : ((blockIdx.z == 1) ? b1 : b2);
    float*       C    = (blockIdx.z == 0) ? C0 : ((blockIdx.z == 1) ? C1 : C2);

    extern __shared__ float smg[];
    float* SAbase = smg;
    float* SBbase = smg + GSTAGES * ASZ;

    const int tid  = threadIdx.x;
    const int wid  = tid >> 5;
    const int lane = tid & 31;
    const int wm   = wid & 1;
    const int wn   = wid >> 1;
    const int gid  = lane >> 2;
    const int tig  = lane & 3;

    const float* Aptr = A  + (long)blockIdx.y * GBM * K;
    const float* Bptr = BT + (long)blockIdx.x * GBN * K;   // W^T rows = n

    // Staging: both tiles are 128 rows x 32 floats.
    const int srow = tid >> 3;            // 0..31, +32 per iter
    const int sc   = (tid & 7) * 4;       // 0..28

    // ldmatrix per-lane row/col selectors (derived from m8n8.b16 layout).
    const int a_row_in = ((lane >> 3) & 1) * 8 + (lane & 7);
    const int a_kofs   = (lane >> 4) * 4;
    const int b_row_in = lane & 7;
    const int b_kofs   = ((lane >> 3) & 1) * 4;

    float acc[4][4][4];
#pragma unroll
    for (int mi = 0; mi < 4; mi++)
#pragma unroll
        for (int ni = 0; ni < 4; ni++)
#pragma unroll
            for (int r = 0; r < 4; r++) acc[mi][ni][r] = 0.f;

    const int NT = K / GBK;

#define GEMM_ISSUE(KT, S)                                                     \
    do {                                                                      \
        float* as_ = SAbase + (S) * ASZ;                                      \
        float* bs_ = SBbase + (S) * BSZ;                                      \
        _Pragma("unroll")                                                     \
        for (int i_ = 0; i_ < 4; i_++) {                                      \
            int r_ = srow + i_ * 32;                                          \
            cp16(as_ + r_ * SAW + sc,                                         \
                 Aptr + (long)r_ * K + (KT) * GBK + sc);                      \
            cp16(bs_ + r_ * SBW + sc,                                         \
                 Bptr + (long)r_ * K + (KT) * GBK + sc);                      \
        }                                                                     \
    } while (0)

#define LOAD_FRAGS(BUF, KB)                                                   \
    do {                                                                      \
        _Pragma("unroll")                                                     \
        for (int mi = 0; mi < 4; mi++)                                        \
            ldm_x4(af[BUF][mi], abase[mi] + (KB) * 4);                        \
        _Pragma("unroll")                                                     \
        for (int ni = 0; ni < 4; ni++)                                        \
            ldm_x2(bf[BUF][ni], bbase[ni] + (KB) * 4);                        \
    } while (0)

    GEMM_ISSUE(0, 0); cp_commit();
    GEMM_ISSUE(1, 1); cp_commit();

    for (int kt = 0; kt < NT; kt++) {
        const int s = kt % GSTAGES;
        if (kt + 2 < NT) cp_wait<1>(); else cp_wait<0>();
        __syncthreads();
        if (kt + 2 < NT) { GEMM_ISSUE(kt + 2, (kt + 2) % GSTAGES); cp_commit(); }

        const uint32_t aS =
            (uint32_t)__cvta_generic_to_shared(SAbase + s * ASZ);
        const uint32_t bS =
            (uint32_t)__cvta_generic_to_shared(SBbase + s * BSZ);
        uint32_t abase[4], bbase[4];
#pragma unroll
        for (int mi = 0; mi < 4; mi++)
            abase[mi] = aS + (uint32_t)(((wm * 64 + mi * 16 + a_row_in) * SAW
                                         + a_kofs) * 4);
#pragma unroll
        for (int ni = 0; ni < 4; ni++)
            bbase[ni] = bS + (uint32_t)(((wn * 32 + ni * 8 + b_row_in) * SBW
                                         + b_kofs) * 4);

        uint32_t af[2][4][4], bf[2][4][2];
        LOAD_FRAGS(0, 0);
#pragma unroll
        for (int ks = 0; ks < 4; ks++) {
            const int cur = ks & 1;
            if (ks < 3) {
                const int nxt = cur ^ 1;
                LOAD_FRAGS(nxt, (ks + 1) * 8);
            }
#pragma unroll
            for (int mi = 0; mi < 4; mi++)
#pragma unroll
                for (int ni = 0; ni < 4; ni++)
                    mma_tf32(acc[mi][ni], af[cur][mi], bf[cur][ni]);
        }
    }
#undef GEMM_ISSUE
#undef LOAD_FRAGS

    const int row_base = blockIdx.y * GBM + wm * 64;
    const int col_base = blockIdx.x * GBN + wn * 32;
#pragma unroll
    for (int mi = 0; mi < 4; mi++) {
#pragma unroll
        for (int ni = 0; ni < 4; ni++) {
            int r0 = row_base + mi * 16 + gid;
            int c  = col_base + ni * 8 + 2 * tig;
            float2 bv = *(const float2*)&bias[c];
            float2 o01, o23;
            o01.x = acc[mi][ni][0] + bv.x;
            o01.y = acc[mi][ni][1] + bv.y;
            o23.x = acc[mi][ni][2] + bv.x;
            o23.y = acc[mi][ni][3] + bv.y;
            if (ROUND_C) {
                o01.x = __uint_as_float(f2tf(o01.x));
                o01.y = __uint_as_float(f2tf(o01.y));
                o23.x = __uint_as_float(f2tf(o23.x));
                o23.y = __uint_as_float(f2tf(o23.y));
            }
            *(float2*)&C[(long)r0 * N + c]       = o01;
            *(float2*)&C[(long)(r0 + 8) * N + c] = o23;
        }
    }
}

// ---------------------------------------------------------------------------
// Tensor-core sliding-window flash attention (unchanged from R16 pass).
// Q-in-registers; K/V cp.async double-buffered, rotating separately.
// ---------------------------------------------------------------------------
#define QT    64
#define ATHR  128
#define SQ_   68
#define SK_   68
#define SV_   72
#define KSZ   (64 * SK_)
#define VSZ   (64 * SV_)
#define ATT_SMEM_BYTES ((QT * SQ_ + 2 * KSZ + 2 * VSZ) * 4)   // 89088

__global__ __launch_bounds__(ATHR, 2)
void attn_tc()
{
    extern __shared__ float sma[];
    uint32_t* Ps = (uint32_t*)sma;                 // [64][68] tf32
    float*    Ks = sma + QT * SQ_;                 // 2 x [64 key][68]
    float*    Vs = Ks + 2 * KSZ;                   // 2 x [64 key][72]

    const int h    = blockIdx.y;
    const int qt   = blockIdx.x;
    const int q0   = qt * QT;
    const int tid  = threadIdx.x;
    const int wid  = tid >> 5;                     // 0..3
    const int lane = tid & 31;
    const int gid  = lane >> 2;
    const int tig  = lane & 3;
    const int col  = h * HD;
    const int qw   = wid * 16;

    const int srow = tid >> 1;            // 0..63  (staging row = key)
    const int sc4  = (tid & 1) * 4;       // base col chunk; +8j covers row

    int kt_lo = qt - 4; if (kt_lo < 0) kt_lo = 0;
    const int kt_hi = qt;
    const bool multi = (kt_lo < kt_hi);

#define ISSUE_K(KT, S)                                                        \
    do {                                                                      \
        long gb_ = (long)((KT) * 64 + srow) * DM + col;                       \
        float* kd_ = Ks + (S) * KSZ + srow * SK_;                             \
        _Pragma("unroll")                                                     \
        for (int j_ = 0; j_ < 8; j_++) {                                      \
            int c_ = sc4 + 8 * j_;                                            \
            cp16(kd_ + c_, &g_k[gb_ + c_]);                                   \
        }                                                                     \
    } while (0)

#define ISSUE_V(KT, S)                                                        \
    do {                                                                      \
        long gb_ = (long)((KT) * 64 + srow) * DM + col;                       \
        float* vd_ = Vs + (S) * VSZ + srow * SV_;                             \
        _Pragma("unroll")                                                     \
        for (int j_ = 0; j_ < 8; j_++) {                                      \
            int c_ = sc4 + 8 * j_;                                            \
            cp16(vd_ + c_, &g_v[gb_ + c_]);                                   \
        }                                                                     \
    } while (0)

#define COMPUTE_S(DST, KSB)                                                   \
    do {                                                                      \
        const uint32_t* ksb_ = (const uint32_t*)(KSB);                        \
        _Pragma("unroll")                                                     \
        for (int ni = 0; ni < 8; ni++)                                        \
            _Pragma("unroll")                                                 \
            for (int r = 0; r < 4; r++) (DST)[ni][r] = 0.f;                   \
        _Pragma("unroll")                                                     \
        for (int ksl = 0; ksl < 8; ksl++) {                                   \
            const int kb = ksl * 8;                                           \
            uint32_t b_[8][2];                                                \
            _Pragma("unroll")                                                 \
            for (int ni = 0; ni < 8; ni++) {                                  \
                int n = ni * 8 + gid;                                         \
                b_[ni][0] = ksb_[n * SK_ + kb + tig];                         \
                b_[ni][1] = ksb_[n * SK_ + kb + tig + 4];                     \
            }                                                                 \
            _Pragma("unroll")                                                 \
            for (int ni = 0; ni < 8; ni++) mma_tf32((DST)[ni], aq[ksl], b_[ni]); \
        }                                                                     \
    } while (0)

    // Prologue commits: G0={K(lo),V(lo)}, then G1a={K(lo+1)}, G1b={V(lo+1)}.
    ISSUE_K(kt_lo, 0); ISSUE_V(kt_lo, 0); cp_commit();
    if (multi) {
        ISSUE_K(kt_lo + 1, 1); cp_commit();
        ISSUE_V(kt_lo + 1, 1); cp_commit();
    }

    // Q a-fragments direct from GMEM (g_q tf32; *0.125 exact).
    uint32_t aq[8][4];
    {
        const float* qrow0 = &g_q[(long)(q0 + qw + gid) * DM + col];
        const float* qrow1 = qrow0 + 8 * DM;
#pragma unroll
        for (int ksl = 0; ksl < 8; ksl++) {
            const int kb = ksl * 8;
            aq[ksl][0] = __float_as_uint(qrow0[kb + tig]     * 0.125f);
            aq[ksl][1] = __float_as_uint(qrow1[kb + tig]     * 0.125f);
            aq[ksl][2] = __float_as_uint(qrow0[kb + tig + 4] * 0.125f);
            aq[ksl][3] = __float_as_uint(qrow1[kb + tig + 4] * 0.125f);
        }
    }

    const int prow0 = (qw + gid) * SQ_;
    const int prow1 = (qw + gid + 8) * SQ_;

    if (multi) cp_wait<2>(); else cp_wait<0>();   // G0 landed
    __syncthreads();                               // K/V(lo) visible

    float sr_cur[8][4], sr_next[8][4];
    COMPUTE_S(sr_cur, Ks + 0 * KSZ);

    float m0 = -1e30f, m1 = -1e30f, l0 = 0.f, l1 = 0.f;
    float o[8][4];
#pragma unroll
    for (int ni = 0; ni < 8; ni++)
#pragma unroll
        for (int r = 0; r < 4; r++) o[ni][r] = 0.f;

    for (int kt = kt_lo; kt <= kt_hi; kt++) {
        const int sk = (kt - kt_lo) & 1;

        if (kt < kt_hi) cp_wait<1>(); else cp_wait<0>();
        __syncthreads();

        if (kt + 2 <= kt_hi) { ISSUE_K(kt + 2, sk); cp_commit(); }

        if (kt < kt_hi) COMPUTE_S(sr_next, Ks + (sk ^ 1) * KSZ);

        const int iq0 = q0 + qw + gid;
        const int iq1 = iq0 + 8;
        float tmax0 = -1e30f, tmax1 = -1e30f;
#pragma unroll
        for (int ni = 0; ni < 8; ni++) {
            int jg = kt * 64 + ni * 8 + 2 * tig;
            bool k0, k1;
            k0 = (jg     <= iq0) && (iq0 - jg     < WIN);
            k1 = (jg + 1 <= iq0) && (iq0 - jg - 1 < WIN);
            sr_cur[ni][0] = k0 ? sr_cur[ni][0] : -1e30f;
            sr_cur[ni][1] = k1 ? sr_cur[ni][1] : -1e30f;
            k0 = (jg     <= iq1) && (iq1 - jg     < WIN);
            k1 = (jg + 1 <= iq1) && (iq1 - jg - 1 < WIN);
            sr_cur[ni][2] = k0 ? sr_cur[ni][2] : -1e30f;
            sr_cur[ni][3] = k1 ? sr_cur[ni][3] : -1e30f;
            tmax0 = fmaxf(tmax0, fmaxf(sr_cur[ni][0], sr_cur[ni][1]));
            tmax1 = fmaxf(tmax1, fmaxf(sr_cur[ni][2], sr_cur[ni][3]));
        }
        tmax0 = fmaxf(tmax0, __shfl_xor_sync(0xffffffffu, tmax0, 1));
        tmax0 = fmaxf(tmax0, __shfl_xor_sync(0xffffffffu, tmax0, 2));
        tmax1 = fmaxf(tmax1, __shfl_xor_sync(0xffffffffu, tmax1, 1));
        tmax1 = fmaxf(tmax1, __shfl_xor_sync(0xffffffffu, tmax1, 2));

        float mn0 = fmaxf(m0, tmax0), mn1 = fmaxf(m1, tmax1);
        float corr0 = __expf(m0 - mn0), corr1 = __expf(m1 - mn1);
        m0 = mn0; m1 = mn1;

        float ls0 = 0.f, ls1 = 0.f;
#pragma unroll
        for (int ni = 0; ni < 8; ni++) {
            int c = ni * 8 + 2 * tig;
            float p0 = (sr_cur[ni][0] > -1e29f) ? __expf(sr_cur[ni][0] - m0) : 0.f;
            float p1 = (sr_cur[ni][1] > -1e29f) ? __expf(sr_cur[ni][1] - m0) : 0.f;
            float p2 = (sr_cur[ni][2] > -1e29f) ? __expf(sr_cur[ni][2] - m1) : 0.f;
            float p3 = (sr_cur[ni][3] > -1e29f) ? __expf(sr_cur[ni][3] - m1) : 0.f;
            Ps[prow0 + c]     = f2tf(p0);
            Ps[prow0 + c + 1] = f2tf(p1);
            Ps[prow1 + c]     = f2tf(p2);
            Ps[prow1 + c + 1] = f2tf(p3);
            ls0 += p0 + p1;
            ls1 += p2 + p3;
        }
        ls0 += __shfl_xor_sync(0xffffffffu, ls0, 1);
        ls0 += __shfl_xor_sync(0xffffffffu, ls0, 2);
        ls1 += __shfl_xor_sync(0xffffffffu, ls1, 1);
        ls1 += __shfl_xor_sync(0xffffffffu, ls1, 2);
        l0 = l0 * corr0 + ls0;
        l1 = l1 * corr1 + ls1;
#pragma unroll
        for (int ni = 0; ni < 8; ni++) {
            o[ni][0] *= corr0; o[ni][1] *= corr0;
            o[ni][2] *= corr1; o[ni][3] *= corr1;
        }

        __syncwarp();

        {
            const uint32_t* vs = (const uint32_t*)(Vs + sk * VSZ);
#pragma unroll
            for (int ksl = 0; ksl < 8; ksl++) {
                const int kb = ksl * 8;
                uint32_t a[4];
                a[0] = Ps[prow0 + kb + tig];
                a[1] = Ps[prow1 + kb + tig];
                a[2] = Ps[prow0 + kb + tig + 4];
                a[3] = Ps[prow1 + kb + tig + 4];
                uint32_t b[8][2];
#pragma unroll
                for (int ni = 0; ni < 8; ni++) {
                    int n = ni * 8 + gid;
                    b[ni][0] = vs[(kb + tig) * SV_ + n];
                    b[ni][1] = vs[(kb + tig + 4) * SV_ + n];
                }
#pragma unroll
                for (int ni = 0; ni < 8; ni++) mma_tf32(o[ni], a, b[ni]);
            }
        }

        __syncthreads();
        if (kt + 2 <= kt_hi) { ISSUE_V(kt + 2, sk); cp_commit(); }

#pragma unroll
        for (int ni = 0; ni < 8; ni++)
#pragma unroll
            for (int r = 0; r < 4; r++) sr_cur[ni][r] = sr_next[ni][r];
    }
#undef ISSUE_K
#undef ISSUE_V
#undef COMPUTE_S

    const float inv0 = 1.f / l0, inv1 = 1.f / l1;
    const int r0 = q0 + qw + gid;
#pragma unroll
    for (int ni = 0; ni < 8; ni++) {
        int c = col + ni * 8 + 2 * tig;
        float2 w0, w1;
        w0.x = __uint_as_float(f2tf(o[ni][0] * inv0));
        w0.y = __uint_as_float(f2tf(o[ni][1] * inv0));
        w1.x = __uint_as_float(f2tf(o[ni][2] * inv1));
        w1.y = __uint_as_float(f2tf(o[ni][3] * inv1));
        *(float2*)&g_att[(long)r0 * DM + c]       = w0;
        *(float2*)&g_att[(long)(r0 + 8) * DM + c] = w1;
    }
}

// ---------------------------------------------------------------------------
// Launch. Input order resolved at runtime from in_sizes (weights DM*DM,
// biases DM): grouped setup_inputs order or interleaved pair order.
// ---------------------------------------------------------------------------
extern "C" void kernel_launch(void* const* d_in, const int* in_sizes, int n_in,
                              void* d_out, int out_size)
{
    const float* x = (const float*)d_in[0];
    const float *Wq, *Wk, *Wv, *Wo, *bq, *bk, *bv, *bo;

    if (in_sizes[2] == DM) {
        Wq = (const float*)d_in[1]; bq = (const float*)d_in[2];
        Wk = (const float*)d_in[3]; bk = (const float*)d_in[4];
        Wv = (const float*)d_in[5]; bv = (const float*)d_in[6];
        Wo = (const float*)d_in[7]; bo = (const float*)d_in[8];
    } else {
        Wq = (const float*)d_in[1]; Wk = (const float*)d_in[2];
        Wv = (const float*)d_in[3]; Wo = (const float*)d_in[4];
        bq = (const float*)d_in[5]; bk = (const float*)d_in[6];
        bv = (const float*)d_in[7]; bo = (const float*)d_in[8];
    }
    float* out = (float*)d_out;

    float *q, *k, *v, *att, *xtf, *wtf;
    cudaGetSymbolAddress((void**)&q,   g_q);
    cudaGetSymbolAddress((void**)&k,   g_k);
    cudaGetSymbolAddress((void**)&v,   g_v);
    cudaGetSymbolAddress((void**)&att, g_att);
    cudaGetSymbolAddress((void**)&xtf, g_xtf);
    cudaGetSymbolAddress((void**)&wtf, g_wtf);

    cudaFuncSetAttribute(gemm_tf32_bias<true>,
                         cudaFuncAttributeMaxDynamicSharedMemorySize,
                         GEMM_SMEM_BYTES);
    cudaFuncSetAttribute(gemm_tf32_bias<false>,
                         cudaFuncAttributeMaxDynamicSharedMemorySize,
                         GEMM_SMEM_BYTES);
    cudaFuncSetAttribute(attn_tc,
                         cudaFuncAttributeMaxDynamicSharedMemorySize,
                         ATT_SMEM_BYTES);

    // Pre-round x; transpose + pre-round weights (n-major for ldmatrix B).
    round_x_kernel<<<SEQ * DM / 4 / 256, 256>>>(x, xtf);
    dim3 gtw(DM / 32, DM / 32, 4);
    roundT_w_kernel<<<gtw, 256>>>(Wq, Wk, Wv, Wo, wtf);

    const float* wq = wtf;
    const float* wk = wtf + (size_t)DM * DM;
    const float* wv = wtf + (size_t)2 * DM * DM;
    const float* wo = wtf + (size_t)3 * DM * DM;

    dim3 gqkv(DM / GBN, SEQ / GBM, 3);
    gemm_tf32_bias<true><<<gqkv, 256, GEMM_SMEM_BYTES>>>(
        xtf, wq, wk, wv, bq, bk, bv, q, k, v, SEQ, DM, DM);

    dim3 gat(SEQ / QT, NH);
    attn_tc<<<gat, ATHR, ATT_SMEM_BYTES>>>();

    dim3 gout(DM / GBN, SEQ / GBM, 1);
    gemm_tf32_bias<false><<<gout, 256, GEMM_SMEM_BYTES>>>(
        att, wo, wo, wo, bo, bo, bo, out, out, out, SEQ, DM, DM);
}